// round 11
// baseline (speedup 1.0000x reference)
#include <cuda_runtime.h>
#include <cuda_fp16.h>
#include <math.h>
#include <stdint.h>

// Problem constants
#define Dd   128
#define Kk   1024
#define Nn   4096
#define Bb   8
#define NIN  256
#define TOK  (Bb * Nn)        // 32768 tokens
#define TPC  128              // tokens per CTA in dist kernel
#define KCH  64               // codes per streamed chunk
#define NCH  (Kk / KCH)       // 16 chunks

#define NUM_OFF (Bb * Dd * Nn)
#define DEN_OFF (Bb * Dd * Nn + Kk * Dd)

// K2 tiling (scalar ze GEMM, proven)
#define NT  64
#define ZSS 132

// padded split layout: 136 fp16 per row = 272B
#define PRS    136
#define ARS_B  272
#define AB     (128 * ARS_B)            // 34816 per A split
#define BB     (KCH * ARS_B)            // 17408 per B split

// fp16 scaled-split constants (exact powers of two)
#define SCL   2048.0f
#define SINV  4.8828125e-4f

// dist kernel smem geometry (bytes)
#define OFF_A    0                      // 2 * AB = 69632
#define OFF_B    69632                  // 2 bufs * 2 * BB = 69632 -> ends 139264
#define OFF_QSQ  139264                 // 4096
#define OFF_QSRT 143360                 // 4096
#define OFF_CNT  147456                 // 4096
#define OFF_IND  151552                 // 512
#define OFF_CD2  152064                 // 4096
#define OFF_CDN  156160                 // 4096
#define OFF_CID  160256                 // 4096
#define OFF_MBAR 164352                 // 3 barriers x 8B
#define SM_TOTAL 164480

// ---------------------------------------------------------------------------
// Device global scratch (no allocations allowed) — padded fp16 split layouts
// ---------------------------------------------------------------------------
__device__ __align__(256) __half g_a0[TOK * PRS];
__device__ __align__(256) __half g_a1[TOK * PRS];
__device__ __align__(256) __half g_e0[Kk * PRS];
__device__ __align__(256) __half g_e1[Kk * PRS];
__device__ float g_zsq[TOK];
__device__ float g_zsrt[TOK];
__device__ float g_qsq[Kk];
__device__ float g_qsrt[Kk];
__device__ float g_zsum[Kk * Dd];
__device__ float g_nsum[Kk];

// ---------------------------------------------------------------------------
// PTX helpers (sm_80/sm_90 baseline only)
// ---------------------------------------------------------------------------
__device__ __forceinline__ uint32_t smem_u32(const void* p) {
    uint32_t a;
    asm("{ .reg .u64 t; cvta.to.shared.u64 t, %1; cvt.u32.u64 %0, t; }" : "=r"(a) : "l"(p));
    return a;
}
#define MBARRIER_INIT(mb, c) \
    asm volatile("mbarrier.init.shared.b64 [%0], %1;" :: "r"((uint32_t)(mb)), "r"((uint32_t)(c)) : "memory")
#define MBARRIER_EXPECT_TX(mb, bytes) \
    asm volatile("mbarrier.arrive.expect_tx.shared.b64 _, [%0], %1;" :: "r"((uint32_t)(mb)), "r"((uint32_t)(bytes)) : "memory")
#define FENCE_PROXY_ASYNC() asm volatile("fence.proxy.async.shared::cta;" ::: "memory")
#define MBARRIER_WAIT_PARITY(mb, ph) do { \
    uint32_t _mb = (uint32_t)(mb), _ph = (uint32_t)(ph), _done; \
    asm volatile("{ .reg .pred p; mbarrier.try_wait.parity.acquire.cta.shared::cta.b64 p, [%1], %2; selp.b32 %0, 1, 0, p; }" \
                 : "=r"(_done) : "r"(_mb), "r"(_ph) : "memory"); \
    if (!_done) { \
        asm volatile("{ .reg .pred P1; WL_%=: mbarrier.try_wait.parity.acquire.cta.shared::cta.b64 P1, [%0], %1, 0x989680; @P1 bra.uni WD_%=; bra.uni WL_%=; WD_%=: }" \
                     :: "r"(_mb), "r"(_ph) : "memory"); \
    } \
} while (0)
#define BULK_G2S(dst, src, bytes, mb) \
    asm volatile("cp.async.bulk.shared::cluster.global.mbarrier::complete_tx::bytes [%0], [%1], %2, [%3];" \
                 :: "r"((uint32_t)(dst)), "l"(src), "r"((uint32_t)(bytes)), "r"((uint32_t)(mb)) : "memory")

__device__ __forceinline__ void ldsm_x4(uint32_t* r, uint32_t addr) {
    asm volatile("ldmatrix.sync.aligned.m8n8.x4.shared.b16 {%0,%1,%2,%3}, [%4];"
        : "=r"(r[0]), "=r"(r[1]), "=r"(r[2]), "=r"(r[3]) : "r"(addr));
}
__device__ __forceinline__ void mma_f16(float* d, const uint32_t* a, const uint32_t* b) {
    asm volatile("mma.sync.aligned.m16n8k16.row.col.f32.f16.f16.f32 "
        "{%0,%1,%2,%3}, {%4,%5,%6,%7}, {%8,%9}, {%0,%1,%2,%3};"
        : "+f"(d[0]), "+f"(d[1]), "+f"(d[2]), "+f"(d[3])
        : "r"(a[0]), "r"(a[1]), "r"(a[2]), "r"(a[3]), "r"(b[0]), "r"(b[1]));
}

// ---------------------------------------------------------------------------
// K1: emb fp16 scaled 2-splits + ||q|| stats + zero EMA scratch
// ---------------------------------------------------------------------------
__global__ void vq_prep_kernel(const float* __restrict__ emb) {
    int k = blockIdx.x, d = threadIdx.x;
    float e = emb[k * Dd + d];
    __half h0 = __float2half_rn(e);
    float r1 = e - __half2float(h0);
    __half h1 = __float2half_rn(r1 * SCL);
    g_e0[k * PRS + d] = h0;
    g_e1[k * PRS + d] = h1;
    g_zsum[k * Dd + d] = 0.f;
    float v = e * e;
    #pragma unroll
    for (int o = 16; o > 0; o >>= 1) v += __shfl_xor_sync(0xffffffffu, v, o);
    __shared__ float sred[4];
    if ((d & 31) == 0) sred[d >> 5] = v;
    __syncthreads();
    if (d == 0) {
        float q = sred[0] + sred[1] + sred[2] + sred[3];
        g_qsq[k] = q;
        g_qsrt[k] = sqrtf(q);
        g_nsum[k] = 0.f;
    }
}

// ---------------------------------------------------------------------------
// K2: scalar fp32 ze GEMM -> fp16 scaled splits + ||ze|| stats (proven core)
// ---------------------------------------------------------------------------
extern __shared__ float smem_f[];

__global__ void __launch_bounds__(256)
vq_ze_kernel(const float* __restrict__ z, const float* __restrict__ W)
{
    float* ze_s = smem_f;                 // [64][132]
    float* Wc   = smem_f + NT * ZSS;      // 128*36
    float* zc   = Wc + 128 * 36;          // 32*68

    const int tid = threadIdx.x;
    const int b   = blockIdx.y;
    const int n0  = blockIdx.x * NT;
    const int T0  = b * Nn + n0;
    const float* zb = z + (size_t)b * NIN * Nn;

    const int tdA = tid >> 4;
    const int tnA = tid & 15;
    const int dA = tdA * 8;
    const int nA = tnA * 4;
    float acc[8][4];
    #pragma unroll
    for (int i = 0; i < 8; i++)
        #pragma unroll
        for (int j = 0; j < 4; j++) acc[i][j] = 0.f;

    for (int c0 = 0; c0 < NIN; c0 += 32) {
        {
            int c4 = (tid & 7) * 4;
            int dr = tid >> 3;
            #pragma unroll
            for (int r = 0; r < 4; r++) {
                int d = dr + 32 * r;
                float4 w = *(const float4*)&W[(size_t)d * NIN + c0 + c4];
                *(float4*)&Wc[d * 36 + c4] = w;
            }
        }
        {
            int q4 = (tid & 15) * 4;
            int ccr = tid >> 4;
            #pragma unroll
            for (int r = 0; r < 2; r++) {
                int cc = ccr + 16 * r;
                float4 v = *(const float4*)&zb[(size_t)(c0 + cc) * Nn + n0 + q4];
                *(float4*)&zc[cc * 68 + q4] = v;
            }
        }
        __syncthreads();
        #pragma unroll 2
        for (int cc = 0; cc < 32; cc += 4) {
            float4 w4[8], z4[4];
            #pragma unroll
            for (int i = 0; i < 8; i++) w4[i] = *(const float4*)&Wc[(dA + i) * 36 + cc];
            #pragma unroll
            for (int u = 0; u < 4; u++) z4[u] = *(const float4*)&zc[(cc + u) * 68 + nA];
            #pragma unroll
            for (int i = 0; i < 8; i++) {
                float4 w = w4[i];
                acc[i][0] = fmaf(w.x, z4[0].x, fmaf(w.y, z4[1].x, fmaf(w.z, z4[2].x, fmaf(w.w, z4[3].x, acc[i][0]))));
                acc[i][1] = fmaf(w.x, z4[0].y, fmaf(w.y, z4[1].y, fmaf(w.z, z4[2].y, fmaf(w.w, z4[3].y, acc[i][1]))));
                acc[i][2] = fmaf(w.x, z4[0].z, fmaf(w.y, z4[1].z, fmaf(w.z, z4[2].z, fmaf(w.w, z4[3].z, acc[i][2]))));
                acc[i][3] = fmaf(w.x, z4[0].w, fmaf(w.y, z4[1].w, fmaf(w.z, z4[2].w, fmaf(w.w, z4[3].w, acc[i][3]))));
            }
        }
        __syncthreads();
    }
    #pragma unroll
    for (int j = 0; j < 4; j++) {
        int n = nA + j;
        float4 v0 = make_float4(acc[0][j], acc[1][j], acc[2][j], acc[3][j]);
        float4 v1 = make_float4(acc[4][j], acc[5][j], acc[6][j], acc[7][j]);
        *(float4*)&ze_s[n * ZSS + dA]     = v0;
        *(float4*)&ze_s[n * ZSS + dA + 4] = v1;
    }
    __syncthreads();

    if (tid < NT) {
        const float* row = &ze_s[tid * ZSS];
        float s = 0.f;
        #pragma unroll 8
        for (int d = 0; d < Dd; d += 4) {
            float4 v = *(const float4*)&row[d];
            s += v.x * v.x + v.y * v.y + v.z * v.z + v.w * v.w;
        }
        g_zsq[T0 + tid]  = s;
        g_zsrt[T0 + tid] = sqrtf(s);
    }

    for (int i = tid; i < NT * Dd; i += 256) {
        int tl = i >> 7;
        int d  = i & 127;
        float e = ze_s[tl * ZSS + d];
        __half h0 = __float2half_rn(e);
        float r1 = e - __half2float(h0);
        __half h1 = __float2half_rn(r1 * SCL);
        size_t gi = (size_t)(T0 + tl) * PRS + d;
        g_a0[gi] = h0; g_a1[gi] = h1;
    }
}

// ---------------------------------------------------------------------------
// K3: fp16 2-split 3-product distance GEMM + top-2 guard + exact refine
// ---------------------------------------------------------------------------
__global__ void __launch_bounds__(256, 1)
vq_dist_kernel(const float* __restrict__ emb, float* __restrict__ out)
{
    extern __shared__ char smem_c[];
    const uint32_t sb = smem_u32(smem_c);
    const int tid  = threadIdx.x;
    const int lane = tid & 31;
    const int w    = tid >> 5;           // 8 warps
    const int wt0  = w * 16;             // warp token base (CTA-local)
    const int T0   = blockIdx.x * TPC;

    float* s_qsq  = (float*)(smem_c + OFF_QSQ);
    float* s_qsrt = (float*)(smem_c + OFF_QSRT);
    int*   s_cnt  = (int*)(smem_c + OFF_CNT);
    int*   s_ind  = (int*)(smem_c + OFF_IND);
    float* c_d2   = (float*)(smem_c + OFF_CD2);
    float* c_dn   = (float*)(smem_c + OFF_CDN);
    int*   c_id   = (int*)(smem_c + OFF_CID);
    const uint32_t mb_a  = sb + OFF_MBAR;
    const uint32_t mb_b0 = sb + OFF_MBAR + 8;
    const uint32_t mb_b1 = sb + OFF_MBAR + 16;

    if (tid == 0) {
        MBARRIER_INIT(mb_a, 1);
        MBARRIER_INIT(mb_b0, 1);
        MBARRIER_INIT(mb_b1, 1);
        FENCE_PROXY_ASYNC();
        MBARRIER_EXPECT_TX(mb_a, 2 * AB);
        BULK_G2S(sb + OFF_A,      (const char*)g_a0 + (size_t)T0 * ARS_B, AB, mb_a);
        BULK_G2S(sb + OFF_A + AB, (const char*)g_a1 + (size_t)T0 * ARS_B, AB, mb_a);
        MBARRIER_EXPECT_TX(mb_b0, 2 * BB);
        BULK_G2S(sb + OFF_B,          (const char*)g_e0, BB, mb_b0);
        BULK_G2S(sb + OFF_B + BB,     (const char*)g_e1, BB, mb_b0);
        MBARRIER_EXPECT_TX(mb_b1, 2 * BB);
        BULK_G2S(sb + OFF_B + 2 * BB, (const char*)g_e0 + BB, BB, mb_b1);
        BULK_G2S(sb + OFF_B + 3 * BB, (const char*)g_e1 + BB, BB, mb_b1);
    }

    for (int i = tid; i < Kk; i += 256) {
        s_cnt[i]  = 0;
        s_qsq[i]  = g_qsq[i];
        s_qsrt[i] = g_qsrt[i];
    }
    const float zsq0 = g_zsq[T0 + wt0 + (lane >> 2)];
    const float zsr0 = g_zsrt[T0 + wt0 + (lane >> 2)];
    const float zsq1 = g_zsq[T0 + wt0 + (lane >> 2) + 8];
    const float zsr1 = g_zsrt[T0 + wt0 + (lane >> 2) + 8];
    __syncthreads();

    uint32_t a_addr[2];
    {
        uint32_t arow = wt0 + (lane & 15);
        uint32_t acol = ((lane >> 4) << 3);
        a_addr[0] = sb + OFF_A +      arow * ARS_B + acol * 2;
        a_addr[1] = sb + OFF_A + AB + arow * ARS_B + acol * 2;
    }
    const uint32_t b_lane_off =
        (uint32_t)(((lane & 7) + ((lane >> 4) << 3)) * ARS_B + (((lane >> 3) & 1) << 4));
    const uint32_t b_base0 = sb + OFF_B + b_lane_off;

    // top-2 state per token slot (cross-multiplied scaled distance)
    float bd2_0 = __int_as_float(0x7f800000), bdn_0 = 1.f;
    float sd2_0 = __int_as_float(0x7f800000), sdn_0 = 1.f;
    int   bid_0 = 1 << 30, sid_0 = 1 << 30;
    float bd2_1 = __int_as_float(0x7f800000), bdn_1 = 1.f;
    float sd2_1 = __int_as_float(0x7f800000), sdn_1 = 1.f;
    int   bid_1 = 1 << 30, sid_1 = 1 << 30;

    MBARRIER_WAIT_PARITY(mb_a, 0);

    for (int cc = 0; cc < NCH; cc++) {
        MBARRIER_WAIT_PARITY((cc & 1) ? mb_b1 : mb_b0, (cc >> 1) & 1);

        float accM[8][4], accS[8][4];
        #pragma unroll
        for (int nt = 0; nt < 8; nt++)
            #pragma unroll
            for (int q = 0; q < 4; q++) { accM[nt][q] = 0.f; accS[nt][q] = 0.f; }

        const uint32_t bbuf = b_base0 + (uint32_t)((cc & 1) * (2 * BB));

        #pragma unroll 2
        for (int ks = 0; ks < 8; ks++) {
            uint32_t a0f[4], a1f[4];
            ldsm_x4(a0f, a_addr[0] + ks * 32);
            ldsm_x4(a1f, a_addr[1] + ks * 32);
            #pragma unroll
            for (int ntp = 0; ntp < 4; ntp++) {
                uint32_t b0f[4], b1f[4];
                uint32_t bt = bbuf + (uint32_t)(ntp * 16 * ARS_B + ks * 32);
                ldsm_x4(b0f, bt);
                ldsm_x4(b1f, bt + BB);
                mma_f16(accM[2 * ntp],     a0f, b0f);
                mma_f16(accM[2 * ntp + 1], a0f, b0f + 2);
                mma_f16(accS[2 * ntp],     a0f, b1f);
                mma_f16(accS[2 * ntp + 1], a0f, b1f + 2);
                mma_f16(accS[2 * ntp],     a1f, b0f);
                mma_f16(accS[2 * ntp + 1], a1f, b0f + 2);
            }
        }

        // fold chunk dots (dot = accM + 2^-11 * accS) into running top-2
        #pragma unroll
        for (int nt = 0; nt < 8; nt++) {
            int cb = cc * KCH + nt * 8 + ((lane & 3) << 1);
            #pragma unroll
            for (int ci = 0; ci < 2; ci++) {
                int k = cb + ci;
                float qs = s_qsq[k];
                float qr = s_qsrt[k];
                {
                    float dotv = fmaf(accS[nt][ci], SINV, accM[nt][ci]);
                    float d2 = fmaxf(fmaf(-2.f, dotv, zsq0 + qs), 0.f);
                    float den = zsr0 + qr, dn2 = den * den;
                    float lb = d2 * bdn_0, rb = bd2_0 * dn2;
                    if (lb < rb || (lb == rb && k < bid_0)) {
                        sd2_0 = bd2_0; sdn_0 = bdn_0; sid_0 = bid_0;
                        bd2_0 = d2; bdn_0 = dn2; bid_0 = k;
                    } else {
                        float ls = d2 * sdn_0, rs = sd2_0 * dn2;
                        if (ls < rs || (ls == rs && k < sid_0)) { sd2_0 = d2; sdn_0 = dn2; sid_0 = k; }
                    }
                }
                {
                    float dotv = fmaf(accS[nt][2 + ci], SINV, accM[nt][2 + ci]);
                    float d2 = fmaxf(fmaf(-2.f, dotv, zsq1 + qs), 0.f);
                    float den = zsr1 + qr, dn2 = den * den;
                    float lb = d2 * bdn_1, rb = bd2_1 * dn2;
                    if (lb < rb || (lb == rb && k < bid_1)) {
                        sd2_1 = bd2_1; sdn_1 = bdn_1; sid_1 = bid_1;
                        bd2_1 = d2; bdn_1 = dn2; bid_1 = k;
                    } else {
                        float ls = d2 * sdn_1, rs = sd2_1 * dn2;
                        if (ls < rs || (ls == rs && k < sid_1)) { sd2_1 = d2; sdn_1 = dn2; sid_1 = k; }
                    }
                }
            }
        }
        __syncthreads();

        if (tid == 0 && cc + 2 < NCH) {
            uint32_t mb = (cc & 1) ? mb_b1 : mb_b0;
            uint32_t dst = sb + OFF_B + (uint32_t)((cc & 1) * (2 * BB));
            size_t so = (size_t)(cc + 2) * BB;
            MBARRIER_EXPECT_TX(mb, 2 * BB);
            BULK_G2S(dst,      (const char*)g_e0 + so, BB, mb);
            BULK_G2S(dst + BB, (const char*)g_e1 + so, BB, mb);
        }
    }

    // publish per-lane top-2 candidates: 4 lanes x 2 = 8 per token
    {
        int q = lane & 3;
        int t0 = wt0 + (lane >> 2);
        int i0 = t0 * 8 + q * 2;
        c_d2[i0] = bd2_0; c_dn[i0] = bdn_0; c_id[i0] = bid_0;
        c_d2[i0 + 1] = sd2_0; c_dn[i0 + 1] = sdn_0; c_id[i0 + 1] = sid_0;
        int i1 = (t0 + 8) * 8 + q * 2;
        c_d2[i1] = bd2_1; c_dn[i1] = bdn_1; c_id[i1] = bid_1;
        c_d2[i1 + 1] = sd2_1; c_dn[i1 + 1] = sdn_1; c_id[i1 + 1] = sid_1;
    }
    __syncthreads();

    // per-token certify / exact-refine
    if (tid < TPC) {
        int tl = tid;
        float qd2[8], qdn[8]; int qid[8];
        #pragma unroll
        for (int i = 0; i < 8; i++) {
            qd2[i] = c_d2[tl * 8 + i];
            qdn[i] = c_dn[tl * 8 + i];
            qid[i] = c_id[tl * 8 + i];
        }
        int b = 0;
        #pragma unroll
        for (int i = 1; i < 8; i++) {
            float lhs = qd2[i] * qdn[b], rhs = qd2[b] * qdn[i];
            if (lhs < rhs || (lhs == rhs && qid[i] < qid[b])) b = i;
        }
        float zsq = g_zsq[T0 + tl], zsr = g_zsrt[T0 + tl];
        unsigned surv = 0;
        float Mb = 1e-5f * zsr * s_qsrt[qid[b]];
        #pragma unroll
        for (int i = 0; i < 8; i++) {
            if (i == b) continue;
            float Mi = 1e-5f * zsr * s_qsrt[qid[i]];
            if ((qd2[i] - Mi) * qdn[b] < (qd2[b] + Mb) * qdn[i]) surv |= 1u << i;
        }
        int winner = qid[b];
        if (surv) {
            const __half* p0 = (const __half*)(smem_c + OFF_A + tl * ARS_B);
            const __half* p1 = (const __half*)(smem_c + OFF_A + AB + tl * ARS_B);
            float wd2 = 0.f, wdn = 1.f; int wid = 1 << 30;
            unsigned set = surv | (1u << b);
            for (int i = 0; i < 8; i++) {
                if (!(set & (1u << i))) continue;
                int k = qid[i];
                const float* er = emb + (size_t)k * Dd;
                float dot = 0.f;
                #pragma unroll 4
                for (int d = 0; d < Dd; d++) {
                    float ze = fmaf(__half2float(p1[d]), SINV, __half2float(p0[d]));
                    dot = fmaf(ze, er[d], dot);
                }
                float d2 = fmaxf(fmaf(-2.f, dot, zsq + s_qsq[k]), 0.f);
                float den = zsr + s_qsrt[k], dn2 = den * den;
                float lhs = d2 * wdn, rhs = wd2 * dn2;
                if (wid == (1 << 30) || lhs < rhs || (lhs == rhs && k < wid)) {
                    wd2 = d2; wdn = dn2; wid = k;
                }
            }
            winner = wid;
        }
        s_ind[tl] = winner;
    }
    __syncthreads();

    if (tid < TPC) atomicAdd(&s_cnt[s_ind[tid]], 1);

    // ---- zq gather + EMA scatter : 2 threads per token ----
    {
        int tl   = tid >> 1;
        int half = tid & 1;
        int ci   = s_ind[tl];
        int token = T0 + tl;
        int b = token >> 12;
        int n = token & (Nn - 1);
        const float4* er = (const float4*)(emb + (size_t)ci * Dd + half * 64);
        float* op = out + (size_t)b * Dd * Nn + n + (size_t)(half * 64) * Nn;
        #pragma unroll 4
        for (int d4 = 0; d4 < 16; d4++) {
            float4 v = er[d4];
            op[(size_t)(d4 * 4 + 0) * Nn] = v.x;
            op[(size_t)(d4 * 4 + 1) * Nn] = v.y;
            op[(size_t)(d4 * 4 + 2) * Nn] = v.z;
            op[(size_t)(d4 * 4 + 3) * Nn] = v.w;
        }
        float* zs = g_zsum + (size_t)ci * Dd + half * 64;
        uint32_t arow = (uint32_t)(tl * ARS_B + half * 128);
        #pragma unroll 2
        for (int c8 = 0; c8 < 8; c8++) {
            uint4 v0 = *(const uint4*)(smem_c + OFF_A + arow + c8 * 16);
            uint4 v1 = *(const uint4*)(smem_c + OFF_A + AB + arow + c8 * 16);
            const __half* p0 = (const __half*)&v0;
            const __half* p1 = (const __half*)&v1;
            #pragma unroll
            for (int e = 0; e < 8; e++) {
                float ze = fmaf(__half2float(p1[e]), SINV, __half2float(p0[e]));
                atomicAdd(&zs[c8 * 8 + e], ze);
            }
        }
    }
    __syncthreads();
    for (int i = tid; i < Kk; i += 256) {
        int c = s_cnt[i];
        if (c) atomicAdd(&g_nsum[i], (float)c);
    }
}

// ---------------------------------------------------------------------------
// K4: finalize EMA outputs
// ---------------------------------------------------------------------------
__global__ void vq_ema_kernel(const float* __restrict__ numer,
                              const float* __restrict__ denom,
                              float* __restrict__ out)
{
    int i = blockIdx.x * blockDim.x + threadIdx.x;
    out[NUM_OFF + i] = 0.99f * numer[i] + 0.01f * g_zsum[i];
    if (i < Kk)
        out[DEN_OFF + i] = 0.99f * denom[i] + 0.01f * g_nsum[i];
}

// ---------------------------------------------------------------------------
extern "C" void kernel_launch(void* const* d_in, const int* in_sizes, int n_in,
                              void* d_out, int out_size)
{
    const float* z     = (const float*)d_in[0];
    const float* W     = (const float*)d_in[1];
    const float* emb   = (const float*)d_in[2];
    const float* numer = (const float*)d_in[3];
    const float* denom = (const float*)d_in[4];
    float* out = (float*)d_out;

    const int ze_smem = (NT * ZSS + 128 * 36 + 32 * 68) * 4;  // 60928 B
    cudaFuncSetAttribute(vq_ze_kernel,
                         cudaFuncAttributeMaxDynamicSharedMemorySize, ze_smem);
    cudaFuncSetAttribute(vq_dist_kernel,
                         cudaFuncAttributeMaxDynamicSharedMemorySize, SM_TOTAL);

    vq_prep_kernel<<<Kk, Dd>>>(emb);
    dim3 gz(Nn / NT, Bb);
    vq_ze_kernel<<<gz, 256, ze_smem>>>(z, W);
    vq_dist_kernel<<<TOK / TPC, 256, SM_TOTAL>>>(emb, out);
    vq_ema_kernel<<<(Kk * Dd) / 256, 256>>>(numer, denom, out);
}

// round 13
// speedup vs baseline: 1.1757x; 1.1757x over previous
#include <cuda_runtime.h>
#include <cuda_fp16.h>
#include <math.h>
#include <stdint.h>

// Problem constants
#define Dd   128
#define Kk   1024
#define Nn   4096
#define Bb   8
#define NIN  256
#define TOK  (Bb * Nn)        // 32768 tokens
#define TPC  64               // tokens per CTA in dist kernel
#define KCH  32               // codes per streamed chunk
#define NCH  (Kk / KCH)       // 32 chunks

#define NUM_OFF (Bb * Dd * Nn)
#define DEN_OFF (Bb * Dd * Nn + Kk * Dd)

// K2 tiling (scalar ze GEMM, proven)
#define NT  64
#define ZSS 132

// padded split layout: 136 fp16 per row = 272B
#define PRS    136
#define ARS_B  272
#define AB     (TPC * ARS_B)            // 17408 per A split
#define BB     (KCH * ARS_B)            // 8704 per B split

// fp16 scaled-split constants (exact powers of two)
#define SCL   2048.0f
#define SINV  4.8828125e-4f

// dist kernel smem geometry (bytes)
#define OFF_A    0                      // 2 * AB = 34816
#define OFF_B    34816                  // 2 bufs * 2 * BB = 34816
#define OFF_QSQ  69632                  // 4096
#define OFF_QSRT 73728                  // 4096
#define OFF_IND  77824                  // 256
#define OFF_CD2  78080                  // 64*8*4 = 2048
#define OFF_CDN  80128                  // 2048
#define OFF_CID  82176                  // 2048
#define OFF_MBAR 84224                  // 3 barriers x 8B
#define SM_TOTAL 84352

// ---------------------------------------------------------------------------
// Device global scratch (no allocations allowed) — padded fp16 split layouts
// ---------------------------------------------------------------------------
__device__ __align__(256) __half g_a0[TOK * PRS];
__device__ __align__(256) __half g_a1[TOK * PRS];
__device__ __align__(256) __half g_e0[Kk * PRS];
__device__ __align__(256) __half g_e1[Kk * PRS];
__device__ float g_zsq[TOK];
__device__ float g_zsrt[TOK];
__device__ float g_qsq[Kk];
__device__ float g_qsrt[Kk];
__device__ float g_zsum[Kk * Dd];
__device__ float g_nsum[Kk];

// ---------------------------------------------------------------------------
// PTX helpers (sm_80/sm_90 baseline only)
// ---------------------------------------------------------------------------
__device__ __forceinline__ uint32_t smem_u32(const void* p) {
    uint32_t a;
    asm("{ .reg .u64 t; cvta.to.shared.u64 t, %1; cvt.u32.u64 %0, t; }" : "=r"(a) : "l"(p));
    return a;
}
#define MBARRIER_INIT(mb, c) \
    asm volatile("mbarrier.init.shared.b64 [%0], %1;" :: "r"((uint32_t)(mb)), "r"((uint32_t)(c)) : "memory")
#define MBARRIER_EXPECT_TX(mb, bytes) \
    asm volatile("mbarrier.arrive.expect_tx.shared.b64 _, [%0], %1;" :: "r"((uint32_t)(mb)), "r"((uint32_t)(bytes)) : "memory")
#define FENCE_PROXY_ASYNC() asm volatile("fence.proxy.async.shared::cta;" ::: "memory")
#define MBARRIER_WAIT_PARITY(mb, ph) do { \
    uint32_t _mb = (uint32_t)(mb), _ph = (uint32_t)(ph), _done; \
    asm volatile("{ .reg .pred p; mbarrier.try_wait.parity.acquire.cta.shared::cta.b64 p, [%1], %2; selp.b32 %0, 1, 0, p; }" \
                 : "=r"(_done) : "r"(_mb), "r"(_ph) : "memory"); \
    if (!_done) { \
        asm volatile("{ .reg .pred P1; WL_%=: mbarrier.try_wait.parity.acquire.cta.shared::cta.b64 P1, [%0], %1, 0x989680; @P1 bra.uni WD_%=; bra.uni WL_%=; WD_%=: }" \
                     :: "r"(_mb), "r"(_ph) : "memory"); \
    } \
} while (0)
#define BULK_G2S(dst, src, bytes, mb) \
    asm volatile("cp.async.bulk.shared::cluster.global.mbarrier::complete_tx::bytes [%0], [%1], %2, [%3];" \
                 :: "r"((uint32_t)(dst)), "l"(src), "r"((uint32_t)(bytes)), "r"((uint32_t)(mb)) : "memory")

__device__ __forceinline__ void ldsm_x4(uint32_t* r, uint32_t addr) {
    asm volatile("ldmatrix.sync.aligned.m8n8.x4.shared.b16 {%0,%1,%2,%3}, [%4];"
        : "=r"(r[0]), "=r"(r[1]), "=r"(r[2]), "=r"(r[3]) : "r"(addr));
}
__device__ __forceinline__ void mma_f16(float* d, const uint32_t* a, const uint32_t* b) {
    asm volatile("mma.sync.aligned.m16n8k16.row.col.f32.f16.f16.f32 "
        "{%0,%1,%2,%3}, {%4,%5,%6,%7}, {%8,%9}, {%0,%1,%2,%3};"
        : "+f"(d[0]), "+f"(d[1]), "+f"(d[2]), "+f"(d[3])
        : "r"(a[0]), "r"(a[1]), "r"(a[2]), "r"(a[3]), "r"(b[0]), "r"(b[1]));
}

// ---------------------------------------------------------------------------
// K1: emb fp16 scaled 2-splits + ||q|| stats + zero EMA scratch
// ---------------------------------------------------------------------------
__global__ void vq_prep_kernel(const float* __restrict__ emb) {
    int k = blockIdx.x, d = threadIdx.x;
    float e = emb[k * Dd + d];
    __half h0 = __float2half_rn(e);
    float r1 = e - __half2float(h0);
    __half h1 = __float2half_rn(r1 * SCL);
    g_e0[k * PRS + d] = h0;
    g_e1[k * PRS + d] = h1;
    g_zsum[k * Dd + d] = 0.f;
    float v = e * e;
    #pragma unroll
    for (int o = 16; o > 0; o >>= 1) v += __shfl_xor_sync(0xffffffffu, v, o);
    __shared__ float sred[4];
    if ((d & 31) == 0) sred[d >> 5] = v;
    __syncthreads();
    if (d == 0) {
        float q = sred[0] + sred[1] + sred[2] + sred[3];
        g_qsq[k] = q;
        g_qsrt[k] = sqrtf(q);
        g_nsum[k] = 0.f;
    }
}

// ---------------------------------------------------------------------------
// K2: scalar fp32 ze GEMM -> fp16 scaled splits + ||ze|| stats (proven core)
// ---------------------------------------------------------------------------
extern __shared__ float smem_f[];

__global__ void __launch_bounds__(256)
vq_ze_kernel(const float* __restrict__ z, const float* __restrict__ W)
{
    float* ze_s = smem_f;                 // [64][132]
    float* Wc   = smem_f + NT * ZSS;      // 128*36
    float* zc   = Wc + 128 * 36;          // 32*68

    const int tid = threadIdx.x;
    const int b   = blockIdx.y;
    const int n0  = blockIdx.x * NT;
    const int T0  = b * Nn + n0;
    const float* zb = z + (size_t)b * NIN * Nn;

    const int tdA = tid >> 4;
    const int tnA = tid & 15;
    const int dA = tdA * 8;
    const int nA = tnA * 4;
    float acc[8][4];
    #pragma unroll
    for (int i = 0; i < 8; i++)
        #pragma unroll
        for (int j = 0; j < 4; j++) acc[i][j] = 0.f;

    for (int c0 = 0; c0 < NIN; c0 += 32) {
        {
            int c4 = (tid & 7) * 4;
            int dr = tid >> 3;
            #pragma unroll
            for (int r = 0; r < 4; r++) {
                int d = dr + 32 * r;
                float4 w = *(const float4*)&W[(size_t)d * NIN + c0 + c4];
                *(float4*)&Wc[d * 36 + c4] = w;
            }
        }
        {
            int q4 = (tid & 15) * 4;
            int ccr = tid >> 4;
            #pragma unroll
            for (int r = 0; r < 2; r++) {
                int cc = ccr + 16 * r;
                float4 v = *(const float4*)&zb[(size_t)(c0 + cc) * Nn + n0 + q4];
                *(float4*)&zc[cc * 68 + q4] = v;
            }
        }
        __syncthreads();
        #pragma unroll 2
        for (int cc = 0; cc < 32; cc += 4) {
            float4 w4[8], z4[4];
            #pragma unroll
            for (int i = 0; i < 8; i++) w4[i] = *(const float4*)&Wc[(dA + i) * 36 + cc];
            #pragma unroll
            for (int u = 0; u < 4; u++) z4[u] = *(const float4*)&zc[(cc + u) * 68 + nA];
            #pragma unroll
            for (int i = 0; i < 8; i++) {
                float4 w = w4[i];
                acc[i][0] = fmaf(w.x, z4[0].x, fmaf(w.y, z4[1].x, fmaf(w.z, z4[2].x, fmaf(w.w, z4[3].x, acc[i][0]))));
                acc[i][1] = fmaf(w.x, z4[0].y, fmaf(w.y, z4[1].y, fmaf(w.z, z4[2].y, fmaf(w.w, z4[3].y, acc[i][1]))));
                acc[i][2] = fmaf(w.x, z4[0].z, fmaf(w.y, z4[1].z, fmaf(w.z, z4[2].z, fmaf(w.w, z4[3].z, acc[i][2]))));
                acc[i][3] = fmaf(w.x, z4[0].w, fmaf(w.y, z4[1].w, fmaf(w.z, z4[2].w, fmaf(w.w, z4[3].w, acc[i][3]))));
            }
        }
        __syncthreads();
    }
    #pragma unroll
    for (int j = 0; j < 4; j++) {
        int n = nA + j;
        float4 v0 = make_float4(acc[0][j], acc[1][j], acc[2][j], acc[3][j]);
        float4 v1 = make_float4(acc[4][j], acc[5][j], acc[6][j], acc[7][j]);
        *(float4*)&ze_s[n * ZSS + dA]     = v0;
        *(float4*)&ze_s[n * ZSS + dA + 4] = v1;
    }
    __syncthreads();

    if (tid < NT) {
        const float* row = &ze_s[tid * ZSS];
        float s = 0.f;
        #pragma unroll 8
        for (int d = 0; d < Dd; d += 4) {
            float4 v = *(const float4*)&row[d];
            s += v.x * v.x + v.y * v.y + v.z * v.z + v.w * v.w;
        }
        g_zsq[T0 + tid]  = s;
        g_zsrt[T0 + tid] = sqrtf(s);
    }

    for (int i = tid; i < NT * Dd; i += 256) {
        int tl = i >> 7;
        int d  = i & 127;
        float e = ze_s[tl * ZSS + d];
        __half h0 = __float2half_rn(e);
        float r1 = e - __half2float(h0);
        __half h1 = __float2half_rn(r1 * SCL);
        size_t gi = (size_t)(T0 + tl) * PRS + d;
        g_a0[gi] = h0; g_a1[gi] = h1;
    }
}

// ---------------------------------------------------------------------------
// K3: fp16 2-split distance GEMM, 2 CTAs/SM, warp pairs split codes
// ---------------------------------------------------------------------------
__global__ void __launch_bounds__(256, 2)
vq_dist_kernel(const float* __restrict__ emb, float* __restrict__ out)
{
    extern __shared__ char smem_c[];
    const uint32_t sb = smem_u32(smem_c);
    const int tid  = threadIdx.x;
    const int lane = tid & 31;
    const int w    = tid >> 5;           // 8 warps
    const int tg   = w & 3;              // token group: tokens [tg*16, tg*16+16)
    const int ch   = w >> 2;             // code half within chunk: [ch*16, ch*16+16)
    const int wt0  = tg * 16;
    const int T0   = blockIdx.x * TPC;

    float* s_qsq  = (float*)(smem_c + OFF_QSQ);
    float* s_qsrt = (float*)(smem_c + OFF_QSRT);
    int*   s_ind  = (int*)(smem_c + OFF_IND);
    float* c_d2   = (float*)(smem_c + OFF_CD2);
    float* c_dn   = (float*)(smem_c + OFF_CDN);
    int*   c_id   = (int*)(smem_c + OFF_CID);
    const uint32_t mb_a  = sb + OFF_MBAR;
    const uint32_t mb_b0 = sb + OFF_MBAR + 8;
    const uint32_t mb_b1 = sb + OFF_MBAR + 16;

    if (tid == 0) {
        MBARRIER_INIT(mb_a, 1);
        MBARRIER_INIT(mb_b0, 1);
        MBARRIER_INIT(mb_b1, 1);
        FENCE_PROXY_ASYNC();
        MBARRIER_EXPECT_TX(mb_a, 2 * AB);
        BULK_G2S(sb + OFF_A,      (const char*)g_a0 + (size_t)T0 * ARS_B, AB, mb_a);
        BULK_G2S(sb + OFF_A + AB, (const char*)g_a1 + (size_t)T0 * ARS_B, AB, mb_a);
        MBARRIER_EXPECT_TX(mb_b0, 2 * BB);
        BULK_G2S(sb + OFF_B,          (const char*)g_e0, BB, mb_b0);
        BULK_G2S(sb + OFF_B + BB,     (const char*)g_e1, BB, mb_b0);
        MBARRIER_EXPECT_TX(mb_b1, 2 * BB);
        BULK_G2S(sb + OFF_B + 2 * BB, (const char*)g_e0 + BB, BB, mb_b1);
        BULK_G2S(sb + OFF_B + 3 * BB, (const char*)g_e1 + BB, BB, mb_b1);
    }

    for (int i = tid; i < Kk; i += 256) {
        s_qsq[i]  = g_qsq[i];
        s_qsrt[i] = g_qsrt[i];
    }
    const float zsq0 = g_zsq[T0 + wt0 + (lane >> 2)];
    const float zsr0 = g_zsrt[T0 + wt0 + (lane >> 2)];
    const float zsq1 = g_zsq[T0 + wt0 + (lane >> 2) + 8];
    const float zsr1 = g_zsrt[T0 + wt0 + (lane >> 2) + 8];
    __syncthreads();

    uint32_t a_addr[2];
    {
        uint32_t arow = wt0 + (lane & 15);
        uint32_t acol = ((lane >> 4) << 3);
        a_addr[0] = sb + OFF_A +      arow * ARS_B + acol * 2;
        a_addr[1] = sb + OFF_A + AB + arow * ARS_B + acol * 2;
    }
    // B x4 over this warp's 16 code rows [ch*16, ch*16+16)
    const uint32_t b_lane_off =
        (uint32_t)((ch * 16 + (lane & 7) + ((lane >> 4) << 3)) * ARS_B + (((lane >> 3) & 1) << 4));
    const uint32_t b_base0 = sb + OFF_B + b_lane_off;

    float bd2_0 = __int_as_float(0x7f800000), bdn_0 = 1.f;
    float bd2_1 = __int_as_float(0x7f800000), bdn_1 = 1.f;
    int   bid_0 = 1 << 30, bid_1 = 1 << 30;

    MBARRIER_WAIT_PARITY(mb_a, 0);

    for (int cc = 0; cc < NCH; cc++) {
        MBARRIER_WAIT_PARITY((cc & 1) ? mb_b1 : mb_b0, (cc >> 1) & 1);

        float accM[2][4], accS[2][4];
        #pragma unroll
        for (int nt = 0; nt < 2; nt++)
            #pragma unroll
            for (int q = 0; q < 4; q++) { accM[nt][q] = 0.f; accS[nt][q] = 0.f; }

        const uint32_t bbuf = b_base0 + (uint32_t)((cc & 1) * (2 * BB));

        #pragma unroll 4
        for (int ks = 0; ks < 8; ks++) {
            uint32_t a0f[4], a1f[4], b0f[4], b1f[4];
            ldsm_x4(a0f, a_addr[0] + ks * 32);
            ldsm_x4(a1f, a_addr[1] + ks * 32);
            ldsm_x4(b0f, bbuf + ks * 32);
            ldsm_x4(b1f, bbuf + BB + ks * 32);
            mma_f16(accM[0], a0f, b0f);
            mma_f16(accM[1], a0f, b0f + 2);
            mma_f16(accS[0], a0f, b1f);
            mma_f16(accS[1], a0f, b1f + 2);
            mma_f16(accS[0], a1f, b0f);
            mma_f16(accS[1], a1f, b0f + 2);
        }

        // fold chunk dots (dot = accM + 2^-11 * accS) into running top-1
        #pragma unroll
        for (int nt = 0; nt < 2; nt++) {
            int cb = cc * KCH + ch * 16 + nt * 8 + ((lane & 3) << 1);
            #pragma unroll
            for (int ci = 0; ci < 2; ci++) {
                int k = cb + ci;
                float qs = s_qsq[k];
                float qr = s_qsrt[k];
                {
                    float dotv = fmaf(accS[nt][ci], SINV, accM[nt][ci]);
                    float d2 = fmaxf(fmaf(-2.f, dotv, zsq0 + qs), 0.f);
                    float den = zsr0 + qr, dn2 = den * den;
                    float lb = d2 * bdn_0, rb = bd2_0 * dn2;
                    if (lb < rb || (lb == rb && k < bid_0)) { bd2_0 = d2; bdn_0 = dn2; bid_0 = k; }
                }
                {
                    float dotv = fmaf(accS[nt][2 + ci], SINV, accM[nt][2 + ci]);
                    float d2 = fmaxf(fmaf(-2.f, dotv, zsq1 + qs), 0.f);
                    float den = zsr1 + qr, dn2 = den * den;
                    float lb = d2 * bdn_1, rb = bd2_1 * dn2;
                    if (lb < rb || (lb == rb && k < bid_1)) { bd2_1 = d2; bdn_1 = dn2; bid_1 = k; }
                }
            }
        }
        __syncthreads();

        if (tid == 0 && cc + 2 < NCH) {
            uint32_t mb = (cc & 1) ? mb_b1 : mb_b0;
            uint32_t dst = sb + OFF_B + (uint32_t)((cc & 1) * (2 * BB));
            size_t so = (size_t)(cc + 2) * BB;
            MBARRIER_EXPECT_TX(mb, 2 * BB);
            BULK_G2S(dst,      (const char*)g_e0 + so, BB, mb);
            BULK_G2S(dst + BB, (const char*)g_e1 + so, BB, mb);
        }
    }

    // publish per-partition top-1: 4 lane-quads x 2 code-halves = 8 per token
    {
        int part = ch * 4 + (lane & 3);
        int t0 = wt0 + (lane >> 2);
        c_d2[t0 * 8 + part] = bd2_0; c_dn[t0 * 8 + part] = bdn_0; c_id[t0 * 8 + part] = bid_0;
        int t1 = t0 + 8;
        c_d2[t1 * 8 + part] = bd2_1; c_dn[t1 * 8 + part] = bdn_1; c_id[t1 * 8 + part] = bid_1;
    }
    __syncthreads();

    // per-token certify / exact-refine
    if (tid < TPC) {
        int tl = tid;
        float qd2[8], qdn[8]; int qid[8];
        #pragma unroll
        for (int i = 0; i < 8; i++) {
            qd2[i] = c_d2[tl * 8 + i];
            qdn[i] = c_dn[tl * 8 + i];
            qid[i] = c_id[tl * 8 + i];
        }
        int b = 0;
        #pragma unroll
        for (int i = 1; i < 8; i++) {
            float lhs = qd2[i] * qdn[b], rhs = qd2[b] * qdn[i];
            if (lhs < rhs || (lhs == rhs && qid[i] < qid[b])) b = i;
        }
        float zsq = g_zsq[T0 + tl], zsr = g_zsrt[T0 + tl];
        unsigned surv = 0;
        float Mb = 1e-5f * zsr * s_qsrt[qid[b]];
        #pragma unroll
        for (int i = 0; i < 8; i++) {
            if (i == b) continue;
            float Mi = 1e-5f * zsr * s_qsrt[qid[i]];
            if ((qd2[i] - Mi) * qdn[b] < (qd2[b] + Mb) * qdn[i]) surv |= 1u << i;
        }
        int winner = qid[b];
        if (surv) {
            const __half* p0 = (const __half*)(smem_c + OFF_A + tl * ARS_B);
            const __half* p1 = (const __half*)(smem_c + OFF_A + AB + tl * ARS_B);
            float wd2 = 0.f, wdn = 1.f; int wid = 1 << 30;
            unsigned set = surv | (1u << b);
            for (int i = 0; i < 8; i++) {
                if (!(set & (1u << i))) continue;
                int k = qid[i];
                const float* er = emb + (size_t)k * Dd;
                float dot = 0.f;
                #pragma unroll 4
                for (int d = 0; d < Dd; d++) {
                    float ze = fmaf(__half2float(p1[d]), SINV, __half2float(p0[d]));
                    dot = fmaf(ze, er[d], dot);
                }
                float d2 = fmaxf(fmaf(-2.f, dot, zsq + s_qsq[k]), 0.f);
                float den = zsr + s_qsrt[k], dn2 = den * den;
                float lhs = d2 * wdn, rhs = wd2 * dn2;
                if (wid == (1 << 30) || lhs < rhs || (lhs == rhs && k < wid)) {
                    wd2 = d2; wdn = dn2; wid = k;
                }
            }
            winner = wid;
        }
        s_ind[tl] = winner;
        atomicAdd(&g_nsum[winner], 1.0f);
    }
    __syncthreads();

    // ---- zq gather + EMA scatter : 4 threads per token ----
    {
        int tl   = tid >> 2;              // 0..63
        int qtr  = tid & 3;               // 32 d's each
        int ci   = s_ind[tl];
        int token = T0 + tl;
        int b = token >> 12;
        int n = token & (Nn - 1);
        const float4* er = (const float4*)(emb + (size_t)ci * Dd + qtr * 32);
        float* op = out + (size_t)b * Dd * Nn + n + (size_t)(qtr * 32) * Nn;
        #pragma unroll 4
        for (int d4 = 0; d4 < 8; d4++) {
            float4 v = er[d4];
            op[(size_t)(d4 * 4 + 0) * Nn] = v.x;
            op[(size_t)(d4 * 4 + 1) * Nn] = v.y;
            op[(size_t)(d4 * 4 + 2) * Nn] = v.z;
            op[(size_t)(d4 * 4 + 3) * Nn] = v.w;
        }
        float* zs = g_zsum + (size_t)ci * Dd + qtr * 32;
        uint32_t arow = (uint32_t)(tl * ARS_B + qtr * 64);
        #pragma unroll
        for (int c8 = 0; c8 < 4; c8++) {
            uint4 v0 = *(const uint4*)(smem_c + OFF_A + arow + c8 * 16);
            uint4 v1 = *(const uint4*)(smem_c + OFF_A + AB + arow + c8 * 16);
            const __half* p0 = (const __half*)&v0;
            const __half* p1 = (const __half*)&v1;
            #pragma unroll
            for (int e = 0; e < 8; e++) {
                float ze = fmaf(__half2float(p1[e]), SINV, __half2float(p0[e]));
                atomicAdd(&zs[c8 * 8 + e], ze);
            }
        }
    }
}

// ---------------------------------------------------------------------------
// K4: finalize EMA outputs
// ---------------------------------------------------------------------------
__global__ void vq_ema_kernel(const float* __restrict__ numer,
                              const float* __restrict__ denom,
                              float* __restrict__ out)
{
    int i = blockIdx.x * blockDim.x + threadIdx.x;
    out[NUM_OFF + i] = 0.99f * numer[i] + 0.01f * g_zsum[i];
    if (i < Kk)
        out[DEN_OFF + i] = 0.99f * denom[i] + 0.01f * g_nsum[i];
}

// ---------------------------------------------------------------------------
extern "C" void kernel_launch(void* const* d_in, const int* in_sizes, int n_in,
                              void* d_out, int out_size)
{
    const float* z     = (const float*)d_in[0];
    const float* W     = (const float*)d_in[1];
    const float* emb   = (const float*)d_in[2];
    const float* numer = (const float*)d_in[3];
    const float* denom = (const float*)d_in[4];
    float* out = (float*)d_out;

    const int ze_smem = (NT * ZSS + 128 * 36 + 32 * 68) * 4;  // 60928 B
    cudaFuncSetAttribute(vq_ze_kernel,
                         cudaFuncAttributeMaxDynamicSharedMemorySize, ze_smem);
    cudaFuncSetAttribute(vq_dist_kernel,
                         cudaFuncAttributeMaxDynamicSharedMemorySize, SM_TOTAL);

    vq_prep_kernel<<<Kk, Dd>>>(emb);
    dim3 gz(Nn / NT, Bb);
    vq_ze_kernel<<<gz, 256, ze_smem>>>(z, W);
    vq_dist_kernel<<<TOK / TPC, 256, SM_TOTAL>>>(emb, out);
    vq_ema_kernel<<<(Kk * Dd) / 256, 256>>>(numer, denom, out);
}

// round 14
// speedup vs baseline: 1.3414x; 1.1409x over previous
#include <cuda_runtime.h>
#include <cuda_fp16.h>
#include <math.h>
#include <stdint.h>

// Problem constants
#define Dd   128
#define Kk   1024
#define Nn   4096
#define Bb   8
#define NIN  256
#define TOK  (Bb * Nn)        // 32768 tokens
#define TPC  64               // tokens per CTA (dist + ze)
#define KCH  32               // codes per streamed chunk (dist)
#define NCH  (Kk / KCH)       // 32 chunks

#define NUM_OFF (Bb * Dd * Nn)
#define DEN_OFF (Bb * Dd * Nn + Kk * Dd)

// padded split layout: 136 fp16 per row = 272B
#define PRS    136
#define ARS_B  272
#define AB     (TPC * ARS_B)            // 17408 per A split
#define BB     (KCH * ARS_B)            // 8704 per B split

// fp16 scaled-split constants (exact powers of two)
#define SCL   2048.0f
#define SINV  4.8828125e-4f

// ---- dist kernel smem geometry (bytes) ----
#define OFF_A    0                      // 2 * AB = 34816
#define OFF_B    34816                  // 2 bufs * 2 * BB = 34816
#define OFF_QSQ  69632                  // 4096
#define OFF_QSRT 73728                  // 4096
#define OFF_IND  77824                  // 256
#define OFF_CD2  78080                  // 2048
#define OFF_CDN  80128                  // 2048
#define OFF_CID  82176                  // 2048
#define OFF_MBAR 84224
#define SM_TOTAL 84352

// ---- ze MMA kernel smem geometry (bytes) ----
#define ZF_OFF   0                      // 2 bufs x 64x68 f32 = 34816 (aliased by ze_s in epilogue)
#define Z16_0    34816                  // [64 tok][72 halves] = 9216
#define Z16_1    44032                  // 9216
#define WB_OFF   53248                  // 2 bufs x 2 splits x (128x72x2=18432) = 73728
#define WCH_B    18432                  // bytes per W split chunk
#define ZMB_OFF  126976                 // 2 mbarriers
#define SM_ZE    127104

// ---------------------------------------------------------------------------
// Device global scratch (no allocations allowed)
// ---------------------------------------------------------------------------
__device__ __align__(256) __half g_a0[TOK * PRS];
__device__ __align__(256) __half g_a1[TOK * PRS];
__device__ __align__(256) __half g_e0[Kk * PRS];
__device__ __align__(256) __half g_e1[Kk * PRS];
__device__ __align__(256) __half g_w0[4 * 128 * 72];   // chunked [kc][d][72]
__device__ __align__(256) __half g_w1[4 * 128 * 72];
__device__ float g_zsq[TOK];
__device__ float g_zsrt[TOK];
__device__ float g_qsq[Kk];
__device__ float g_qsrt[Kk];
__device__ float g_zsum[Kk * Dd];
__device__ float g_nsum[Kk];

// ---------------------------------------------------------------------------
// PTX helpers (sm_80/sm_90 baseline only)
// ---------------------------------------------------------------------------
__device__ __forceinline__ uint32_t smem_u32(const void* p) {
    uint32_t a;
    asm("{ .reg .u64 t; cvta.to.shared.u64 t, %1; cvt.u32.u64 %0, t; }" : "=r"(a) : "l"(p));
    return a;
}
#define MBARRIER_INIT(mb, c) \
    asm volatile("mbarrier.init.shared.b64 [%0], %1;" :: "r"((uint32_t)(mb)), "r"((uint32_t)(c)) : "memory")
#define MBARRIER_EXPECT_TX(mb, bytes) \
    asm volatile("mbarrier.arrive.expect_tx.shared.b64 _, [%0], %1;" :: "r"((uint32_t)(mb)), "r"((uint32_t)(bytes)) : "memory")
#define FENCE_PROXY_ASYNC() asm volatile("fence.proxy.async.shared::cta;" ::: "memory")
#define MBARRIER_WAIT_PARITY(mb, ph) do { \
    uint32_t _mb = (uint32_t)(mb), _ph = (uint32_t)(ph), _done; \
    asm volatile("{ .reg .pred p; mbarrier.try_wait.parity.acquire.cta.shared::cta.b64 p, [%1], %2; selp.b32 %0, 1, 0, p; }" \
                 : "=r"(_done) : "r"(_mb), "r"(_ph) : "memory"); \
    if (!_done) { \
        asm volatile("{ .reg .pred P1; WL_%=: mbarrier.try_wait.parity.acquire.cta.shared::cta.b64 P1, [%0], %1, 0x989680; @P1 bra.uni WD_%=; bra.uni WL_%=; WD_%=: }" \
                     :: "r"(_mb), "r"(_ph) : "memory"); \
    } \
} while (0)
#define BULK_G2S(dst, src, bytes, mb) \
    asm volatile("cp.async.bulk.shared::cluster.global.mbarrier::complete_tx::bytes [%0], [%1], %2, [%3];" \
                 :: "r"((uint32_t)(dst)), "l"(src), "r"((uint32_t)(bytes)), "r"((uint32_t)(mb)) : "memory")
#define CP16(dst, src) \
    asm volatile("cp.async.cg.shared.global [%0], [%1], 16;" :: "r"(dst), "l"(src))
#define CP_COMMIT() asm volatile("cp.async.commit_group;" ::: "memory")
#define CP_WAIT0()  asm volatile("cp.async.wait_group 0;" ::: "memory")
#define CP_WAIT1()  asm volatile("cp.async.wait_group 1;" ::: "memory")

__device__ __forceinline__ void ldsm_x4(uint32_t* r, uint32_t addr) {
    asm volatile("ldmatrix.sync.aligned.m8n8.x4.shared.b16 {%0,%1,%2,%3}, [%4];"
        : "=r"(r[0]), "=r"(r[1]), "=r"(r[2]), "=r"(r[3]) : "r"(addr));
}
__device__ __forceinline__ void mma_f16(float* d, const uint32_t* a, const uint32_t* b) {
    asm volatile("mma.sync.aligned.m16n8k16.row.col.f32.f16.f16.f32 "
        "{%0,%1,%2,%3}, {%4,%5,%6,%7}, {%8,%9}, {%0,%1,%2,%3};"
        : "+f"(d[0]), "+f"(d[1]), "+f"(d[2]), "+f"(d[3])
        : "r"(a[0]), "r"(a[1]), "r"(a[2]), "r"(a[3]), "r"(b[0]), "r"(b[1]));
}

// ---------------------------------------------------------------------------
// K1a: emb fp16 scaled 2-splits + ||q|| stats + zero EMA scratch
// ---------------------------------------------------------------------------
__global__ void vq_prep_kernel(const float* __restrict__ emb) {
    int k = blockIdx.x, d = threadIdx.x;
    float e = emb[k * Dd + d];
    __half h0 = __float2half_rn(e);
    float r1 = e - __half2float(h0);
    __half h1 = __float2half_rn(r1 * SCL);
    g_e0[k * PRS + d] = h0;
    g_e1[k * PRS + d] = h1;
    g_zsum[k * Dd + d] = 0.f;
    float v = e * e;
    #pragma unroll
    for (int o = 16; o > 0; o >>= 1) v += __shfl_xor_sync(0xffffffffu, v, o);
    __shared__ float sred[4];
    if ((d & 31) == 0) sred[d >> 5] = v;
    __syncthreads();
    if (d == 0) {
        float q = sred[0] + sred[1] + sred[2] + sred[3];
        g_qsq[k] = q;
        g_qsrt[k] = sqrtf(q);
        g_nsum[k] = 0.f;
    }
}

// ---------------------------------------------------------------------------
// K1b: W fp16 scaled 2-splits, chunked layout [kc][d][72]
// ---------------------------------------------------------------------------
__global__ void vq_prep_w_kernel(const float* __restrict__ W) {
    int d = blockIdx.x;       // 0..127
    int c = threadIdx.x;      // 0..255
    float e = W[d * NIN + c];
    __half h0 = __float2half_rn(e);
    float r1 = e - __half2float(h0);
    __half h1 = __float2half_rn(r1 * SCL);
    int idx = (c >> 6) * (128 * 72) + d * 72 + (c & 63);
    g_w0[idx] = h0;
    g_w1[idx] = h1;
}

// ---------------------------------------------------------------------------
// K2: tensor-core ze GEMM (fp16 2-split, 3 products) -> splits + norms
// Output per CTA: 64 tokens x 128 d.  8 warps: tg=w&3 tokens, dh=w>>2 d-half.
// ---------------------------------------------------------------------------
__global__ void __launch_bounds__(256, 1)
vq_ze_mma(const float* __restrict__ z)
{
    extern __shared__ char smem_c[];
    const uint32_t sb = smem_u32(smem_c);
    const int tid  = threadIdx.x;
    const int lane = tid & 31;
    const int w8   = tid >> 5;
    const int tg   = w8 & 3;
    const int dh   = w8 >> 2;
    const int T0   = blockIdx.x * TPC;
    const int b    = T0 >> 12;
    const int n0   = T0 & (Nn - 1);
    const float* zb = z + (size_t)b * NIN * Nn + n0;

    const uint32_t mb_w0 = sb + ZMB_OFF;
    const uint32_t mb_w1 = sb + ZMB_OFF + 8;

    if (tid == 0) {
        MBARRIER_INIT(mb_w0, 1);
        MBARRIER_INIT(mb_w1, 1);
        FENCE_PROXY_ASYNC();
        MBARRIER_EXPECT_TX(mb_w0, 2 * WCH_B);
        BULK_G2S(sb + WB_OFF,          (const char*)g_w0, WCH_B, mb_w0);
        BULK_G2S(sb + WB_OFF + WCH_B,  (const char*)g_w1, WCH_B, mb_w0);
        MBARRIER_EXPECT_TX(mb_w1, 2 * WCH_B);
        BULK_G2S(sb + WB_OFF + 2 * WCH_B, (const char*)g_w0 + WCH_B, WCH_B, mb_w1);
        BULK_G2S(sb + WB_OFF + 3 * WCH_B, (const char*)g_w1 + WCH_B, WCH_B, mb_w1);
    }

    // stage z chunks 0,1 (fp32, [64 c][64 tok], row stride 272B)
    #pragma unroll
    for (int pc = 0; pc < 2; pc++) {
        for (int i = tid; i < 1024; i += 256) {
            int r = i >> 4, cl = i & 15;
            CP16(sb + ZF_OFF + pc * 17408 + r * 272 + cl * 16,
                 (const char*)(zb + (size_t)(pc * 64 + r) * Nn) + cl * 16);
        }
        CP_COMMIT();
    }
    __syncthreads();   // mbarrier init visible

    float accM[8][4], accS[8][4];
    #pragma unroll
    for (int nt = 0; nt < 8; nt++)
        #pragma unroll
        for (int q = 0; q < 4; q++) { accM[nt][q] = 0.f; accS[nt][q] = 0.f; }

    // ldmatrix addresses
    const uint32_t a_row = (uint32_t)(tg * 16 + (lane & 15));
    const uint32_t a_off0 = sb + Z16_0 + a_row * 144 + (((lane >> 4) << 3) << 1);
    const uint32_t a_off1 = sb + Z16_1 + a_row * 144 + (((lane >> 4) << 3) << 1);
    const uint32_t b_lane = (uint32_t)(((lane & 7) + ((lane >> 4) << 3)) * 144 + (((lane >> 3) & 1) << 4));

    for (int kc = 0; kc < 4; kc++) {
        // wait this chunk's z fp32 tile
        if (kc < 3) { CP_WAIT1(); } else { CP_WAIT0(); }
        __syncthreads();

        // convert + transpose: zf[c][tok] -> z16 splits [tok][c]
        {
            const float* zf = (const float*)(smem_c + ZF_OFF + (kc & 1) * 17408);
            __half* o0 = (__half*)(smem_c + Z16_0);
            __half* o1 = (__half*)(smem_c + Z16_1);
            #pragma unroll
            for (int i = tid; i < 4096; i += 256) {
                int tok = i & 63, c = i >> 6;
                float e = zf[c * 68 + tok];
                __half h0 = __float2half_rn(e);
                float r1 = e - __half2float(h0);
                __half h1 = __float2half_rn(r1 * SCL);
                o0[tok * 72 + c] = h0;
                o1[tok * 72 + c] = h1;
            }
        }
        __syncthreads();

        MBARRIER_WAIT_PARITY((kc & 1) ? mb_w1 : mb_w0, (kc >> 1) & 1);

        const uint32_t wb = sb + WB_OFF + (uint32_t)((kc & 1) * 2 * WCH_B);
        #pragma unroll
        for (int ks = 0; ks < 4; ks++) {
            uint32_t a0f[4], a1f[4];
            ldsm_x4(a0f, a_off0 + ks * 32);
            ldsm_x4(a1f, a_off1 + ks * 32);
            #pragma unroll
            for (int nt2 = 0; nt2 < 4; nt2++) {
                uint32_t w0f[4], w1f[4];
                uint32_t bt = wb + (uint32_t)((dh * 64 + nt2 * 16) * 144) + b_lane + ks * 32;
                ldsm_x4(w0f, bt);
                ldsm_x4(w1f, bt + WCH_B);
                mma_f16(accM[2 * nt2],     a0f, w0f);
                mma_f16(accM[2 * nt2 + 1], a0f, w0f + 2);
                mma_f16(accS[2 * nt2],     a0f, w1f);
                mma_f16(accS[2 * nt2 + 1], a0f, w1f + 2);
                mma_f16(accS[2 * nt2],     a1f, w0f);
                mma_f16(accS[2 * nt2 + 1], a1f, w0f + 2);
            }
        }
        __syncthreads();   // done with z16 + this W buf

        // prefetch chunk kc+2
        if (kc + 2 < 4) {
            for (int i = tid; i < 1024; i += 256) {
                int r = i >> 4, cl = i & 15;
                CP16(sb + ZF_OFF + (kc & 1) * 17408 + r * 272 + cl * 16,
                     (const char*)(zb + (size_t)((kc + 2) * 64 + r) * Nn) + cl * 16);
            }
            CP_COMMIT();
            if (tid == 0) {
                uint32_t mb = (kc & 1) ? mb_w1 : mb_w0;
                uint32_t dst = sb + WB_OFF + (uint32_t)((kc & 1) * 2 * WCH_B);
                MBARRIER_EXPECT_TX(mb, 2 * WCH_B);
                BULK_G2S(dst,         (const char*)g_w0 + (kc + 2) * WCH_B, WCH_B, mb);
                BULK_G2S(dst + WCH_B, (const char*)g_w1 + (kc + 2) * WCH_B, WCH_B, mb);
            }
        }
    }

    // ---- fragments -> ze_s fp32 [64 tok][132] (aliases ZF region) ----
    {
        float* ze_s = (float*)(smem_c + ZF_OFF);
        int r0 = tg * 16 + (lane >> 2);
        int cb = dh * 64 + 2 * (lane & 3);
        #pragma unroll
        for (int nt = 0; nt < 8; nt++) {
            int col = cb + nt * 8;
            ze_s[r0 * 132 + col]           = fmaf(accS[nt][0], SINV, accM[nt][0]);
            ze_s[r0 * 132 + col + 1]       = fmaf(accS[nt][1], SINV, accM[nt][1]);
            ze_s[(r0 + 8) * 132 + col]     = fmaf(accS[nt][2], SINV, accM[nt][2]);
            ze_s[(r0 + 8) * 132 + col + 1] = fmaf(accS[nt][3], SINV, accM[nt][3]);
        }
    }
    __syncthreads();

    // ---- norms + fp16 splits to gmem (identical to proven epilogue) ----
    {
        const float* ze_s = (const float*)(smem_c + ZF_OFF);
        if (tid < TPC) {
            const float* row = &ze_s[tid * 132];
            float s = 0.f;
            #pragma unroll 8
            for (int d = 0; d < Dd; d += 4) {
                float4 v = *(const float4*)&row[d];
                s += v.x * v.x + v.y * v.y + v.z * v.z + v.w * v.w;
            }
            g_zsq[T0 + tid]  = s;
            g_zsrt[T0 + tid] = sqrtf(s);
        }
        for (int i = tid; i < TPC * Dd; i += 256) {
            int tl = i >> 7;
            int d  = i & 127;
            float e = ze_s[tl * 132 + d];
            __half h0 = __float2half_rn(e);
            float r1 = e - __half2float(h0);
            __half h1 = __float2half_rn(r1 * SCL);
            size_t gi = (size_t)(T0 + tl) * PRS + d;
            g_a0[gi] = h0; g_a1[gi] = h1;
        }
    }
}

// ---------------------------------------------------------------------------
// K3: fp16 2-split distance GEMM, 2 CTAs/SM (proven R11 version, unchanged)
// ---------------------------------------------------------------------------
__global__ void __launch_bounds__(256, 2)
vq_dist_kernel(const float* __restrict__ emb, float* __restrict__ out)
{
    extern __shared__ char smem_c[];
    const uint32_t sb = smem_u32(smem_c);
    const int tid  = threadIdx.x;
    const int lane = tid & 31;
    const int w    = tid >> 5;
    const int tg   = w & 3;
    const int ch   = w >> 2;
    const int wt0  = tg * 16;
    const int T0   = blockIdx.x * TPC;

    float* s_qsq  = (float*)(smem_c + OFF_QSQ);
    float* s_qsrt = (float*)(smem_c + OFF_QSRT);
    int*   s_ind  = (int*)(smem_c + OFF_IND);
    float* c_d2   = (float*)(smem_c + OFF_CD2);
    float* c_dn   = (float*)(smem_c + OFF_CDN);
    int*   c_id   = (int*)(smem_c + OFF_CID);
    const uint32_t mb_a  = sb + OFF_MBAR;
    const uint32_t mb_b0 = sb + OFF_MBAR + 8;
    const uint32_t mb_b1 = sb + OFF_MBAR + 16;

    if (tid == 0) {
        MBARRIER_INIT(mb_a, 1);
        MBARRIER_INIT(mb_b0, 1);
        MBARRIER_INIT(mb_b1, 1);
        FENCE_PROXY_ASYNC();
        MBARRIER_EXPECT_TX(mb_a, 2 * AB);
        BULK_G2S(sb + OFF_A,      (const char*)g_a0 + (size_t)T0 * ARS_B, AB, mb_a);
        BULK_G2S(sb + OFF_A + AB, (const char*)g_a1 + (size_t)T0 * ARS_B, AB, mb_a);
        MBARRIER_EXPECT_TX(mb_b0, 2 * BB);
        BULK_G2S(sb + OFF_B,          (const char*)g_e0, BB, mb_b0);
        BULK_G2S(sb + OFF_B + BB,     (const char*)g_e1, BB, mb_b0);
        MBARRIER_EXPECT_TX(mb_b1, 2 * BB);
        BULK_G2S(sb + OFF_B + 2 * BB, (const char*)g_e0 + BB, BB, mb_b1);
        BULK_G2S(sb + OFF_B + 3 * BB, (const char*)g_e1 + BB, BB, mb_b1);
    }

    for (int i = tid; i < Kk; i += 256) {
        s_qsq[i]  = g_qsq[i];
        s_qsrt[i] = g_qsrt[i];
    }
    const float zsq0 = g_zsq[T0 + wt0 + (lane >> 2)];
    const float zsr0 = g_zsrt[T0 + wt0 + (lane >> 2)];
    const float zsq1 = g_zsq[T0 + wt0 + (lane >> 2) + 8];
    const float zsr1 = g_zsrt[T0 + wt0 + (lane >> 2) + 8];
    __syncthreads();

    uint32_t a_addr[2];
    {
        uint32_t arow = wt0 + (lane & 15);
        uint32_t acol = ((lane >> 4) << 3);
        a_addr[0] = sb + OFF_A +      arow * ARS_B + acol * 2;
        a_addr[1] = sb + OFF_A + AB + arow * ARS_B + acol * 2;
    }
    const uint32_t b_lane_off =
        (uint32_t)((ch * 16 + (lane & 7) + ((lane >> 4) << 3)) * ARS_B + (((lane >> 3) & 1) << 4));
    const uint32_t b_base0 = sb + OFF_B + b_lane_off;

    float bd2_0 = __int_as_float(0x7f800000), bdn_0 = 1.f;
    float bd2_1 = __int_as_float(0x7f800000), bdn_1 = 1.f;
    int   bid_0 = 1 << 30, bid_1 = 1 << 30;

    MBARRIER_WAIT_PARITY(mb_a, 0);

    for (int cc = 0; cc < NCH; cc++) {
        MBARRIER_WAIT_PARITY((cc & 1) ? mb_b1 : mb_b0, (cc >> 1) & 1);

        float accM[2][4], accS[2][4];
        #pragma unroll
        for (int nt = 0; nt < 2; nt++)
            #pragma unroll
            for (int q = 0; q < 4; q++) { accM[nt][q] = 0.f; accS[nt][q] = 0.f; }

        const uint32_t bbuf = b_base0 + (uint32_t)((cc & 1) * (2 * BB));

        #pragma unroll 4
        for (int ks = 0; ks < 8; ks++) {
            uint32_t a0f[4], a1f[4], b0f[4], b1f[4];
            ldsm_x4(a0f, a_addr[0] + ks * 32);
            ldsm_x4(a1f, a_addr[1] + ks * 32);
            ldsm_x4(b0f, bbuf + ks * 32);
            ldsm_x4(b1f, bbuf + BB + ks * 32);
            mma_f16(accM[0], a0f, b0f);
            mma_f16(accM[1], a0f, b0f + 2);
            mma_f16(accS[0], a0f, b1f);
            mma_f16(accS[1], a0f, b1f + 2);
            mma_f16(accS[0], a1f, b0f);
            mma_f16(accS[1], a1f, b0f + 2);
        }

        #pragma unroll
        for (int nt = 0; nt < 2; nt++) {
            int cb = cc * KCH + ch * 16 + nt * 8 + ((lane & 3) << 1);
            #pragma unroll
            for (int ci = 0; ci < 2; ci++) {
                int k = cb + ci;
                float qs = s_qsq[k];
                float qr = s_qsrt[k];
                {
                    float dotv = fmaf(accS[nt][ci], SINV, accM[nt][ci]);
                    float d2 = fmaxf(fmaf(-2.f, dotv, zsq0 + qs), 0.f);
                    float den = zsr0 + qr, dn2 = den * den;
                    float lb = d2 * bdn_0, rb = bd2_0 * dn2;
                    if (lb < rb || (lb == rb && k < bid_0)) { bd2_0 = d2; bdn_0 = dn2; bid_0 = k; }
                }
                {
                    float dotv = fmaf(accS[nt][2 + ci], SINV, accM[nt][2 + ci]);
                    float d2 = fmaxf(fmaf(-2.f, dotv, zsq1 + qs), 0.f);
                    float den = zsr1 + qr, dn2 = den * den;
                    float lb = d2 * bdn_1, rb = bd2_1 * dn2;
                    if (lb < rb || (lb == rb && k < bid_1)) { bd2_1 = d2; bdn_1 = dn2; bid_1 = k; }
                }
            }
        }
        __syncthreads();

        if (tid == 0 && cc + 2 < NCH) {
            uint32_t mb = (cc & 1) ? mb_b1 : mb_b0;
            uint32_t dst = sb + OFF_B + (uint32_t)((cc & 1) * (2 * BB));
            size_t so = (size_t)(cc + 2) * BB;
            MBARRIER_EXPECT_TX(mb, 2 * BB);
            BULK_G2S(dst,      (const char*)g_e0 + so, BB, mb);
            BULK_G2S(dst + BB, (const char*)g_e1 + so, BB, mb);
        }
    }

    {
        int part = ch * 4 + (lane & 3);
        int t0 = wt0 + (lane >> 2);
        c_d2[t0 * 8 + part] = bd2_0; c_dn[t0 * 8 + part] = bdn_0; c_id[t0 * 8 + part] = bid_0;
        int t1 = t0 + 8;
        c_d2[t1 * 8 + part] = bd2_1; c_dn[t1 * 8 + part] = bdn_1; c_id[t1 * 8 + part] = bid_1;
    }
    __syncthreads();

    if (tid < TPC) {
        int tl = tid;
        float qd2[8], qdn[8]; int qid[8];
        #pragma unroll
        for (int i = 0; i < 8; i++) {
            qd2[i] = c_d2[tl * 8 + i];
            qdn[i] = c_dn[tl * 8 + i];
            qid[i] = c_id[tl * 8 + i];
        }
        int b = 0;
        #pragma unroll
        for (int i = 1; i < 8; i++) {
            float lhs = qd2[i] * qdn[b], rhs = qd2[b] * qdn[i];
            if (lhs < rhs || (lhs == rhs && qid[i] < qid[b])) b = i;
        }
        float zsq = g_zsq[T0 + tl], zsr = g_zsrt[T0 + tl];
        unsigned surv = 0;
        float Mb = 1e-5f * zsr * s_qsrt[qid[b]];
        #pragma unroll
        for (int i = 0; i < 8; i++) {
            if (i == b) continue;
            float Mi = 1e-5f * zsr * s_qsrt[qid[i]];
            if ((qd2[i] - Mi) * qdn[b] < (qd2[b] + Mb) * qdn[i]) surv |= 1u << i;
        }
        int winner = qid[b];
        if (surv) {
            const __half* p0 = (const __half*)(smem_c + OFF_A + tl * ARS_B);
            const __half* p1 = (const __half*)(smem_c + OFF_A + AB + tl * ARS_B);
            float wd2 = 0.f, wdn = 1.f; int wid = 1 << 30;
            unsigned set = surv | (1u << b);
            for (int i = 0; i < 8; i++) {
                if (!(set & (1u << i))) continue;
                int k = qid[i];
                const float* er = emb + (size_t)k * Dd;
                float dot = 0.f;
                #pragma unroll 4
                for (int d = 0; d < Dd; d++) {
                    float ze = fmaf(__half2float(p1[d]), SINV, __half2float(p0[d]));
                    dot = fmaf(ze, er[d], dot);
                }
                float d2 = fmaxf(fmaf(-2.f, dot, zsq + s_qsq[k]), 0.f);
                float den = zsr + s_qsrt[k], dn2 = den * den;
                float lhs = d2 * wdn, rhs = wd2 * dn2;
                if (wid == (1 << 30) || lhs < rhs || (lhs == rhs && k < wid)) {
                    wd2 = d2; wdn = dn2; wid = k;
                }
            }
            winner = wid;
        }
        s_ind[tl] = winner;
        atomicAdd(&g_nsum[winner], 1.0f);
    }
    __syncthreads();

    {
        int tl   = tid >> 2;
        int qtr  = tid & 3;
        int ci   = s_ind[tl];
        int token = T0 + tl;
        int b = token >> 12;
        int n = token & (Nn - 1);
        const float4* er = (const float4*)(emb + (size_t)ci * Dd + qtr * 32);
        float* op = out + (size_t)b * Dd * Nn + n + (size_t)(qtr * 32) * Nn;
        #pragma unroll 4
        for (int d4 = 0; d4 < 8; d4++) {
            float4 v = er[d4];
            op[(size_t)(d4 * 4 + 0) * Nn] = v.x;
            op[(size_t)(d4 * 4 + 1) * Nn] = v.y;
            op[(size_t)(d4 * 4 + 2) * Nn] = v.z;
            op[(size_t)(d4 * 4 + 3) * Nn] = v.w;
        }
        float* zs = g_zsum + (size_t)ci * Dd + qtr * 32;
        uint32_t arow = (uint32_t)(tl * ARS_B + qtr * 64);
        #pragma unroll
        for (int c8 = 0; c8 < 4; c8++) {
            uint4 v0 = *(const uint4*)(smem_c + OFF_A + arow + c8 * 16);
            uint4 v1 = *(const uint4*)(smem_c + OFF_A + AB + arow + c8 * 16);
            const __half* p0 = (const __half*)&v0;
            const __half* p1 = (const __half*)&v1;
            #pragma unroll
            for (int e = 0; e < 8; e++) {
                float ze = fmaf(__half2float(p1[e]), SINV, __half2float(p0[e]));
                atomicAdd(&zs[c8 * 8 + e], ze);
            }
        }
    }
}

// ---------------------------------------------------------------------------
// K4: finalize EMA outputs
// ---------------------------------------------------------------------------
__global__ void vq_ema_kernel(const float* __restrict__ numer,
                              const float* __restrict__ denom,
                              float* __restrict__ out)
{
    int i = blockIdx.x * blockDim.x + threadIdx.x;
    out[NUM_OFF + i] = 0.99f * numer[i] + 0.01f * g_zsum[i];
    if (i < Kk)
        out[DEN_OFF + i] = 0.99f * denom[i] + 0.01f * g_nsum[i];
}

// ---------------------------------------------------------------------------
extern "C" void kernel_launch(void* const* d_in, const int* in_sizes, int n_in,
                              void* d_out, int out_size)
{
    const float* z     = (const float*)d_in[0];
    const float* W     = (const float*)d_in[1];
    const float* emb   = (const float*)d_in[2];
    const float* numer = (const float*)d_in[3];
    const float* denom = (const float*)d_in[4];
    float* out = (float*)d_out;

    cudaFuncSetAttribute(vq_ze_mma,
                         cudaFuncAttributeMaxDynamicSharedMemorySize, SM_ZE);
    cudaFuncSetAttribute(vq_dist_kernel,
                         cudaFuncAttributeMaxDynamicSharedMemorySize, SM_TOTAL);

    vq_prep_kernel<<<Kk, Dd>>>(emb);
    vq_prep_w_kernel<<<Dd, NIN>>>(W);
    vq_ze_mma<<<TOK / TPC, 256, SM_ZE>>>(z);
    vq_dist_kernel<<<TOK / TPC, 256, SM_TOTAL>>>(emb, out);
    vq_ema_kernel<<<(Kk * Dd) / 256, 256>>>(numer, denom, out);
}

// round 16
// speedup vs baseline: 1.4043x; 1.0469x over previous
#include <cuda_runtime.h>
#include <cuda_fp16.h>
#include <math.h>
#include <stdint.h>

// Problem constants
#define Dd   128
#define Kk   1024
#define Nn   4096
#define Bb   8
#define NIN  256
#define TOK  (Bb * Nn)        // 32768 tokens
#define TPC  64               // tokens per CTA (dist + ze)
#define KCH  64               // codes per streamed chunk (dist)
#define NCH  (Kk / KCH)       // 16 chunks

#define NUM_OFF (Bb * Dd * Nn)
#define DEN_OFF (Bb * Dd * Nn + Kk * Dd)

// padded split layout: 136 fp16 per row = 272B
#define PRS    136
#define ARS_B  272
#define AB     (TPC * ARS_B)            // 17408 per A split
#define BB     (KCH * ARS_B)            // 17408 per B split (64 codes)

// fp16 scaled-split constants (exact powers of two)
#define SCL   2048.0f
#define SINV  4.8828125e-4f

// ---- dist kernel smem geometry (bytes) ----
#define OFF_A    0                      // 2 * AB = 34816
#define OFF_B    34816                  // 2 bufs * 2 splits * BB = 69632 -> ends 104448
#define OFF_QSQ  104448                 // 4096
#define OFF_QSRT 108544                 // 4096
#define OFF_MBAR 112640                 // 5 barriers x 8B
#define OFF_IND  112704                 // 256
#define SM_TOTAL 112960
// post-loop aliases into dead B region:
#define OFF_CD2  OFF_B
#define OFF_CDN  (OFF_B + 2048)
#define OFF_CID  (OFF_B + 4096)

// ---- ze MMA kernel smem geometry (bytes) ----
#define ZF_OFF   0
#define Z16_0    34816
#define Z16_1    44032
#define WB_OFF   53248
#define WCH_B    18432
#define ZMB_OFF  126976
#define SM_ZE    127104

// ---------------------------------------------------------------------------
// Device global scratch (no allocations allowed)
// ---------------------------------------------------------------------------
__device__ __align__(256) __half g_a0[TOK * PRS];
__device__ __align__(256) __half g_a1[TOK * PRS];
__device__ __align__(256) __half g_e0[Kk * PRS];
__device__ __align__(256) __half g_e1[Kk * PRS];
__device__ __align__(256) __half g_w0[4 * 128 * 72];
__device__ __align__(256) __half g_w1[4 * 128 * 72];
__device__ float g_zsq[TOK];
__device__ float g_zsrt[TOK];
__device__ float g_qsq[Kk];
__device__ float g_qsrt[Kk];
__device__ float g_zsum[Kk * Dd];
__device__ float g_nsum[Kk];

// ---------------------------------------------------------------------------
// PTX helpers (sm_80/sm_90 baseline only)
// ---------------------------------------------------------------------------
__device__ __forceinline__ uint32_t smem_u32(const void* p) {
    uint32_t a;
    asm("{ .reg .u64 t; cvta.to.shared.u64 t, %1; cvt.u32.u64 %0, t; }" : "=r"(a) : "l"(p));
    return a;
}
#define MBARRIER_INIT(mb, c) \
    asm volatile("mbarrier.init.shared.b64 [%0], %1;" :: "r"((uint32_t)(mb)), "r"((uint32_t)(c)) : "memory")
#define MBARRIER_EXPECT_TX(mb, bytes) \
    asm volatile("mbarrier.arrive.expect_tx.shared.b64 _, [%0], %1;" :: "r"((uint32_t)(mb)), "r"((uint32_t)(bytes)) : "memory")
#define MBARRIER_ARRIVE(mb) \
    asm volatile("mbarrier.arrive.release.cta.shared.b64 _, [%0];" :: "r"((uint32_t)(mb)) : "memory")
#define FENCE_PROXY_ASYNC() asm volatile("fence.proxy.async.shared::cta;" ::: "memory")
#define MBARRIER_WAIT_PARITY(mb, ph) do { \
    uint32_t _mb = (uint32_t)(mb), _ph = (uint32_t)(ph), _done; \
    asm volatile("{ .reg .pred p; mbarrier.try_wait.parity.acquire.cta.shared::cta.b64 p, [%1], %2; selp.b32 %0, 1, 0, p; }" \
                 : "=r"(_done) : "r"(_mb), "r"(_ph) : "memory"); \
    if (!_done) { \
        asm volatile("{ .reg .pred P1; WL_%=: mbarrier.try_wait.parity.acquire.cta.shared::cta.b64 P1, [%0], %1, 0x989680; @P1 bra.uni WD_%=; bra.uni WL_%=; WD_%=: }" \
                     :: "r"(_mb), "r"(_ph) : "memory"); \
    } \
} while (0)
#define BULK_G2S(dst, src, bytes, mb) \
    asm volatile("cp.async.bulk.shared::cluster.global.mbarrier::complete_tx::bytes [%0], [%1], %2, [%3];" \
                 :: "r"((uint32_t)(dst)), "l"(src), "r"((uint32_t)(bytes)), "r"((uint32_t)(mb)) : "memory")
#define CP16(dst, src) \
    asm volatile("cp.async.cg.shared.global [%0], [%1], 16;" :: "r"(dst), "l"(src))
#define CP_COMMIT() asm volatile("cp.async.commit_group;" ::: "memory")
#define CP_WAIT0()  asm volatile("cp.async.wait_group 0;" ::: "memory")
#define CP_WAIT1()  asm volatile("cp.async.wait_group 1;" ::: "memory")

__device__ __forceinline__ void ldsm_x4(uint32_t* r, uint32_t addr) {
    asm volatile("ldmatrix.sync.aligned.m8n8.x4.shared.b16 {%0,%1,%2,%3}, [%4];"
        : "=r"(r[0]), "=r"(r[1]), "=r"(r[2]), "=r"(r[3]) : "r"(addr));
}
__device__ __forceinline__ void mma_f16(float* d, const uint32_t* a, const uint32_t* b) {
    asm volatile("mma.sync.aligned.m16n8k16.row.col.f32.f16.f16.f32 "
        "{%0,%1,%2,%3}, {%4,%5,%6,%7}, {%8,%9}, {%0,%1,%2,%3};"
        : "+f"(d[0]), "+f"(d[1]), "+f"(d[2]), "+f"(d[3])
        : "r"(a[0]), "r"(a[1]), "r"(a[2]), "r"(a[3]), "r"(b[0]), "r"(b[1]));
}

// ---------------------------------------------------------------------------
// K1a: emb fp16 scaled 2-splits + ||q|| stats + zero EMA scratch
// ---------------------------------------------------------------------------
__global__ void vq_prep_kernel(const float* __restrict__ emb) {
    int k = blockIdx.x, d = threadIdx.x;
    float e = emb[k * Dd + d];
    __half h0 = __float2half_rn(e);
    float r1 = e - __half2float(h0);
    __half h1 = __float2half_rn(r1 * SCL);
    g_e0[k * PRS + d] = h0;
    g_e1[k * PRS + d] = h1;
    g_zsum[k * Dd + d] = 0.f;
    float v = e * e;
    #pragma unroll
    for (int o = 16; o > 0; o >>= 1) v += __shfl_xor_sync(0xffffffffu, v, o);
    __shared__ float sred[4];
    if ((d & 31) == 0) sred[d >> 5] = v;
    __syncthreads();
    if (d == 0) {
        float q = sred[0] + sred[1] + sred[2] + sred[3];
        g_qsq[k] = q;
        g_qsrt[k] = sqrtf(q);
        g_nsum[k] = 0.f;
    }
}

// ---------------------------------------------------------------------------
// K1b: W fp16 scaled 2-splits, chunked layout [kc][d][72]
// ---------------------------------------------------------------------------
__global__ void vq_prep_w_kernel(const float* __restrict__ W) {
    int d = blockIdx.x;
    int c = threadIdx.x;
    float e = W[d * NIN + c];
    __half h0 = __float2half_rn(e);
    float r1 = e - __half2float(h0);
    __half h1 = __float2half_rn(r1 * SCL);
    int idx = (c >> 6) * (128 * 72) + d * 72 + (c & 63);
    g_w0[idx] = h0;
    g_w1[idx] = h1;
}

// ---------------------------------------------------------------------------
// K2: tensor-core ze GEMM (proven R13 version, unchanged)
// ---------------------------------------------------------------------------
__global__ void __launch_bounds__(256, 1)
vq_ze_mma(const float* __restrict__ z)
{
    extern __shared__ char smem_c[];
    const uint32_t sb = smem_u32(smem_c);
    const int tid  = threadIdx.x;
    const int lane = tid & 31;
    const int w8   = tid >> 5;
    const int tg   = w8 & 3;
    const int dh   = w8 >> 2;
    const int T0   = blockIdx.x * TPC;
    const int b    = T0 >> 12;
    const int n0   = T0 & (Nn - 1);
    const float* zb = z + (size_t)b * NIN * Nn + n0;

    const uint32_t mb_w0 = sb + ZMB_OFF;
    const uint32_t mb_w1 = sb + ZMB_OFF + 8;

    if (tid == 0) {
        MBARRIER_INIT(mb_w0, 1);
        MBARRIER_INIT(mb_w1, 1);
        FENCE_PROXY_ASYNC();
        MBARRIER_EXPECT_TX(mb_w0, 2 * WCH_B);
        BULK_G2S(sb + WB_OFF,          (const char*)g_w0, WCH_B, mb_w0);
        BULK_G2S(sb + WB_OFF + WCH_B,  (const char*)g_w1, WCH_B, mb_w0);
        MBARRIER_EXPECT_TX(mb_w1, 2 * WCH_B);
        BULK_G2S(sb + WB_OFF + 2 * WCH_B, (const char*)g_w0 + WCH_B, WCH_B, mb_w1);
        BULK_G2S(sb + WB_OFF + 3 * WCH_B, (const char*)g_w1 + WCH_B, WCH_B, mb_w1);
    }

    #pragma unroll
    for (int pc = 0; pc < 2; pc++) {
        for (int i = tid; i < 1024; i += 256) {
            int r = i >> 4, cl = i & 15;
            CP16(sb + ZF_OFF + pc * 17408 + r * 272 + cl * 16,
                 (const char*)(zb + (size_t)(pc * 64 + r) * Nn) + cl * 16);
        }
        CP_COMMIT();
    }
    __syncthreads();

    float accM[8][4], accS[8][4];
    #pragma unroll
    for (int nt = 0; nt < 8; nt++)
        #pragma unroll
        for (int q = 0; q < 4; q++) { accM[nt][q] = 0.f; accS[nt][q] = 0.f; }

    const uint32_t a_row = (uint32_t)(tg * 16 + (lane & 15));
    const uint32_t a_off0 = sb + Z16_0 + a_row * 144 + (((lane >> 4) << 3) << 1);
    const uint32_t a_off1 = sb + Z16_1 + a_row * 144 + (((lane >> 4) << 3) << 1);
    const uint32_t b_lane = (uint32_t)(((lane & 7) + ((lane >> 4) << 3)) * 144 + (((lane >> 3) & 1) << 4));

    for (int kc = 0; kc < 4; kc++) {
        if (kc < 3) { CP_WAIT1(); } else { CP_WAIT0(); }
        __syncthreads();

        {
            const float* zf = (const float*)(smem_c + ZF_OFF + (kc & 1) * 17408);
            __half* o0 = (__half*)(smem_c + Z16_0);
            __half* o1 = (__half*)(smem_c + Z16_1);
            #pragma unroll
            for (int i = tid; i < 4096; i += 256) {
                int tok = i & 63, c = i >> 6;
                float e = zf[c * 68 + tok];
                __half h0 = __float2half_rn(e);
                float r1 = e - __half2float(h0);
                __half h1 = __float2half_rn(r1 * SCL);
                o0[tok * 72 + c] = h0;
                o1[tok * 72 + c] = h1;
            }
        }
        __syncthreads();

        MBARRIER_WAIT_PARITY((kc & 1) ? mb_w1 : mb_w0, (kc >> 1) & 1);

        const uint32_t wb = sb + WB_OFF + (uint32_t)((kc & 1) * 2 * WCH_B);
        #pragma unroll
        for (int ks = 0; ks < 4; ks++) {
            uint32_t a0f[4], a1f[4];
            ldsm_x4(a0f, a_off0 + ks * 32);
            ldsm_x4(a1f, a_off1 + ks * 32);
            #pragma unroll
            for (int nt2 = 0; nt2 < 4; nt2++) {
                uint32_t w0f[4], w1f[4];
                uint32_t bt = wb + (uint32_t)((dh * 64 + nt2 * 16) * 144) + b_lane + ks * 32;
                ldsm_x4(w0f, bt);
                ldsm_x4(w1f, bt + WCH_B);
                mma_f16(accM[2 * nt2],     a0f, w0f);
                mma_f16(accM[2 * nt2 + 1], a0f, w0f + 2);
                mma_f16(accS[2 * nt2],     a0f, w1f);
                mma_f16(accS[2 * nt2 + 1], a0f, w1f + 2);
                mma_f16(accS[2 * nt2],     a1f, w0f);
                mma_f16(accS[2 * nt2 + 1], a1f, w0f + 2);
            }
        }
        __syncthreads();

        if (kc + 2 < 4) {
            for (int i = tid; i < 1024; i += 256) {
                int r = i >> 4, cl = i & 15;
                CP16(sb + ZF_OFF + (kc & 1) * 17408 + r * 272 + cl * 16,
                     (const char*)(zb + (size_t)((kc + 2) * 64 + r) * Nn) + cl * 16);
            }
            CP_COMMIT();
            if (tid == 0) {
                uint32_t mb = (kc & 1) ? mb_w1 : mb_w0;
                uint32_t dst = sb + WB_OFF + (uint32_t)((kc & 1) * 2 * WCH_B);
                MBARRIER_EXPECT_TX(mb, 2 * WCH_B);
                BULK_G2S(dst,         (const char*)g_w0 + (kc + 2) * WCH_B, WCH_B, mb);
                BULK_G2S(dst + WCH_B, (const char*)g_w1 + (kc + 2) * WCH_B, WCH_B, mb);
            }
        }
    }

    {
        float* ze_s = (float*)(smem_c + ZF_OFF);
        int r0 = tg * 16 + (lane >> 2);
        int cb = dh * 64 + 2 * (lane & 3);
        #pragma unroll
        for (int nt = 0; nt < 8; nt++) {
            int col = cb + nt * 8;
            ze_s[r0 * 132 + col]           = fmaf(accS[nt][0], SINV, accM[nt][0]);
            ze_s[r0 * 132 + col + 1]       = fmaf(accS[nt][1], SINV, accM[nt][1]);
            ze_s[(r0 + 8) * 132 + col]     = fmaf(accS[nt][2], SINV, accM[nt][2]);
            ze_s[(r0 + 8) * 132 + col + 1] = fmaf(accS[nt][3], SINV, accM[nt][3]);
        }
    }
    __syncthreads();

    {
        const float* ze_s = (const float*)(smem_c + ZF_OFF);
        if (tid < TPC) {
            const float* row = &ze_s[tid * 132];
            float s = 0.f;
            #pragma unroll 8
            for (int d = 0; d < Dd; d += 4) {
                float4 v = *(const float4*)&row[d];
                s += v.x * v.x + v.y * v.y + v.z * v.z + v.w * v.w;
            }
            g_zsq[T0 + tid]  = s;
            g_zsrt[T0 + tid] = sqrtf(s);
        }
        for (int i = tid; i < TPC * Dd; i += 256) {
            int tl = i >> 7;
            int d  = i & 127;
            float e = ze_s[tl * 132 + d];
            __half h0 = __float2half_rn(e);
            float r1 = e - __half2float(h0);
            __half h1 = __float2half_rn(r1 * SCL);
            size_t gi = (size_t)(T0 + tl) * PRS + d;
            g_a0[gi] = h0; g_a1[gi] = h1;
        }
    }
}

// ---------------------------------------------------------------------------
// K3: fp16 2-split distance GEMM, 64-code chunks, sync-free mainloop
// ---------------------------------------------------------------------------
__global__ void __launch_bounds__(256, 2)
vq_dist_kernel(const float* __restrict__ emb, float* __restrict__ out)
{
    extern __shared__ char smem_c[];
    const uint32_t sb = smem_u32(smem_c);
    const int tid  = threadIdx.x;
    const int lane = tid & 31;
    const int w    = tid >> 5;
    const int tg   = w & 3;              // token group (16 tokens)
    const int ch   = w >> 2;             // code half (32 codes of 64)
    const int wt0  = tg * 16;
    const int T0   = blockIdx.x * TPC;

    float* s_qsq  = (float*)(smem_c + OFF_QSQ);
    float* s_qsrt = (float*)(smem_c + OFF_QSRT);
    int*   s_ind  = (int*)(smem_c + OFF_IND);
    float* c_d2   = (float*)(smem_c + OFF_CD2);
    float* c_dn   = (float*)(smem_c + OFF_CDN);
    int*   c_id   = (int*)(smem_c + OFF_CID);
    const uint32_t mb_a   = sb + OFF_MBAR;
    const uint32_t mb_b0  = sb + OFF_MBAR + 8;
    const uint32_t mb_b1  = sb + OFF_MBAR + 16;
    const uint32_t mb_c0  = sb + OFF_MBAR + 24;   // consumed, count 8
    const uint32_t mb_c1  = sb + OFF_MBAR + 32;

    if (tid == 0) {
        MBARRIER_INIT(mb_a, 1);
        MBARRIER_INIT(mb_b0, 1);
        MBARRIER_INIT(mb_b1, 1);
        MBARRIER_INIT(mb_c0, 8);
        MBARRIER_INIT(mb_c1, 8);
        FENCE_PROXY_ASYNC();
        MBARRIER_EXPECT_TX(mb_a, 2 * AB);
        BULK_G2S(sb + OFF_A,      (const char*)g_a0 + (size_t)T0 * ARS_B, AB, mb_a);
        BULK_G2S(sb + OFF_A + AB, (const char*)g_a1 + (size_t)T0 * ARS_B, AB, mb_a);
        MBARRIER_EXPECT_TX(mb_b0, 2 * BB);
        BULK_G2S(sb + OFF_B,          (const char*)g_e0, BB, mb_b0);
        BULK_G2S(sb + OFF_B + BB,     (const char*)g_e1, BB, mb_b0);
        MBARRIER_EXPECT_TX(mb_b1, 2 * BB);
        BULK_G2S(sb + OFF_B + 2 * BB, (const char*)g_e0 + BB, BB, mb_b1);
        BULK_G2S(sb + OFF_B + 3 * BB, (const char*)g_e1 + BB, BB, mb_b1);
    }

    for (int i = tid; i < Kk; i += 256) {
        s_qsq[i]  = g_qsq[i];
        s_qsrt[i] = g_qsrt[i];
    }
    const float zsq0 = g_zsq[T0 + wt0 + (lane >> 2)];
    const float zsr0 = g_zsrt[T0 + wt0 + (lane >> 2)];
    const float zsq1 = g_zsq[T0 + wt0 + (lane >> 2) + 8];
    const float zsr1 = g_zsrt[T0 + wt0 + (lane >> 2) + 8];
    __syncthreads();   // barrier inits + norm tables visible

    uint32_t a_addr[2];
    {
        uint32_t arow = wt0 + (lane & 15);
        uint32_t acol = ((lane >> 4) << 3);
        a_addr[0] = sb + OFF_A +      arow * ARS_B + acol * 2;
        a_addr[1] = sb + OFF_A + AB + arow * ARS_B + acol * 2;
    }
    // warp's 32 code rows start at ch*32; two 16-row ldsm tiles
    const uint32_t b_lane_off =
        (uint32_t)((ch * 32 + (lane & 7) + ((lane >> 4) << 3)) * ARS_B + (((lane >> 3) & 1) << 4));
    const uint32_t b_base0 = sb + OFF_B + b_lane_off;

    float bd2_0 = __int_as_float(0x7f800000), bdn_0 = 1.f;
    float bd2_1 = __int_as_float(0x7f800000), bdn_1 = 1.f;
    int   bid_0 = 1 << 30, bid_1 = 1 << 30;

    MBARRIER_WAIT_PARITY(mb_a, 0);

    for (int cc = 0; cc < NCH; cc++) {
        MBARRIER_WAIT_PARITY((cc & 1) ? mb_b1 : mb_b0, (cc >> 1) & 1);

        float accM[4][4], accS[4][4];
        #pragma unroll
        for (int nt = 0; nt < 4; nt++)
            #pragma unroll
            for (int q = 0; q < 4; q++) { accM[nt][q] = 0.f; accS[nt][q] = 0.f; }

        const uint32_t bbuf = b_base0 + (uint32_t)((cc & 1) * (2 * BB));

        #pragma unroll 2
        for (int ks = 0; ks < 8; ks++) {
            uint32_t a0f[4], a1f[4], b0f[4], b0g[4], b1f[4], b1g[4];
            ldsm_x4(a0f, a_addr[0] + ks * 32);
            ldsm_x4(a1f, a_addr[1] + ks * 32);
            ldsm_x4(b0f, bbuf + ks * 32);
            ldsm_x4(b0g, bbuf + 16 * ARS_B + ks * 32);
            ldsm_x4(b1f, bbuf + BB + ks * 32);
            ldsm_x4(b1g, bbuf + BB + 16 * ARS_B + ks * 32);
            mma_f16(accM[0], a0f, b0f);
            mma_f16(accM[1], a0f, b0f + 2);
            mma_f16(accM[2], a0f, b0g);
            mma_f16(accM[3], a0f, b0g + 2);
            mma_f16(accS[0], a0f, b1f);
            mma_f16(accS[1], a0f, b1f + 2);
            mma_f16(accS[2], a0f, b1g);
            mma_f16(accS[3], a0f, b1g + 2);
            mma_f16(accS[0], a1f, b0f);
            mma_f16(accS[1], a1f, b0f + 2);
            mma_f16(accS[2], a1f, b0g);
            mma_f16(accS[3], a1f, b0g + 2);
        }

        // this warp is done reading buffer (cc&1)
        if (lane == 0) MBARRIER_ARRIVE((cc & 1) ? mb_c1 : mb_c0);

        // fold chunk dots into running top-1 per partition
        #pragma unroll
        for (int nt = 0; nt < 4; nt++) {
            int cb = cc * KCH + ch * 32 + nt * 8 + ((lane & 3) << 1);
            #pragma unroll
            for (int ci = 0; ci < 2; ci++) {
                int k = cb + ci;
                float qs = s_qsq[k];
                float qr = s_qsrt[k];
                {
                    float dotv = fmaf(accS[nt][ci], SINV, accM[nt][ci]);
                    float d2 = fmaxf(fmaf(-2.f, dotv, zsq0 + qs), 0.f);
                    float den = zsr0 + qr, dn2 = den * den;
                    float lb = d2 * bdn_0, rb = bd2_0 * dn2;
                    if (lb < rb || (lb == rb && k < bid_0)) { bd2_0 = d2; bdn_0 = dn2; bid_0 = k; }
                }
                {
                    float dotv = fmaf(accS[nt][2 + ci], SINV, accM[nt][2 + ci]);
                    float d2 = fmaxf(fmaf(-2.f, dotv, zsq1 + qs), 0.f);
                    float den = zsr1 + qr, dn2 = den * den;
                    float lb = d2 * bdn_1, rb = bd2_1 * dn2;
                    if (lb < rb || (lb == rb && k < bid_1)) { bd2_1 = d2; bdn_1 = dn2; bid_1 = k; }
                }
            }
        }

        // producer refills freed buffer for chunk cc+2
        if (tid == 0 && cc + 2 < NCH) {
            MBARRIER_WAIT_PARITY((cc & 1) ? mb_c1 : mb_c0, (cc >> 1) & 1);
            uint32_t mb = (cc & 1) ? mb_b1 : mb_b0;
            uint32_t dst = sb + OFF_B + (uint32_t)((cc & 1) * (2 * BB));
            size_t so = (size_t)(cc + 2) * BB;
            MBARRIER_EXPECT_TX(mb, 2 * BB);
            BULK_G2S(dst,      (const char*)g_e0 + so, BB, mb);
            BULK_G2S(dst + BB, (const char*)g_e1 + so, BB, mb);
        }
    }

    __syncthreads();   // all warps done with B region before aliasing candidates

    {
        int part = ch * 4 + (lane & 3);
        int t0 = wt0 + (lane >> 2);
        c_d2[t0 * 8 + part] = bd2_0; c_dn[t0 * 8 + part] = bdn_0; c_id[t0 * 8 + part] = bid_0;
        int t1 = t0 + 8;
        c_d2[t1 * 8 + part] = bd2_1; c_dn[t1 * 8 + part] = bdn_1; c_id[t1 * 8 + part] = bid_1;
    }
    __syncthreads();

    if (tid < TPC) {
        int tl = tid;
        float qd2[8], qdn[8]; int qid[8];
        #pragma unroll
        for (int i = 0; i < 8; i++) {
            qd2[i] = c_d2[tl * 8 + i];
            qdn[i] = c_dn[tl * 8 + i];
            qid[i] = c_id[tl * 8 + i];
        }
        int b = 0;
        #pragma unroll
        for (int i = 1; i < 8; i++) {
            float lhs = qd2[i] * qdn[b], rhs = qd2[b] * qdn[i];
            if (lhs < rhs || (lhs == rhs && qid[i] < qid[b])) b = i;
        }
        float zsq = g_zsq[T0 + tl], zsr = g_zsrt[T0 + tl];
        unsigned surv = 0;
        float Mb = 1e-5f * zsr * s_qsrt[qid[b]];
        #pragma unroll
        for (int i = 0; i < 8; i++) {
            if (i == b) continue;
            float Mi = 1e-5f * zsr * s_qsrt[qid[i]];
            if ((qd2[i] - Mi) * qdn[b] < (qd2[b] + Mb) * qdn[i]) surv |= 1u << i;
        }
        int winner = qid[b];
        if (surv) {
            const __half* p0 = (const __half*)(smem_c + OFF_A + tl * ARS_B);
            const __half* p1 = (const __half*)(smem_c + OFF_A + AB + tl * ARS_B);
            float wd2 = 0.f, wdn = 1.f; int wid = 1 << 30;
            unsigned set = surv | (1u << b);
            for (int i = 0; i < 8; i++) {
                if (!(set & (1u << i))) continue;
                int k = qid[i];
                const float* er = emb + (size_t)k * Dd;
                float dot = 0.f;
                #pragma unroll 4
                for (int d = 0; d < Dd; d++) {
                    float ze = fmaf(__half2float(p1[d]), SINV, __half2float(p0[d]));
                    dot = fmaf(ze, er[d], dot);
                }
                float d2 = fmaxf(fmaf(-2.f, dot, zsq + s_qsq[k]), 0.f);
                float den = zsr + s_qsrt[k], dn2 = den * den;
                float lhs = d2 * wdn, rhs = wd2 * dn2;
                if (wid == (1 << 30) || lhs < rhs || (lhs == rhs && k < wid)) {
                    wd2 = d2; wdn = dn2; wid = k;
                }
            }
            winner = wid;
        }
        s_ind[tl] = winner;
        atomicAdd(&g_nsum[winner], 1.0f);
    }
    __syncthreads();

    {
        int tl   = tid >> 2;
        int qtr  = tid & 3;
        int ci   = s_ind[tl];
        int token = T0 + tl;
        int b = token >> 12;
        int n = token & (Nn - 1);
        const float4* er = (const float4*)(emb + (size_t)ci * Dd + qtr * 32);
        float* op = out + (size_t)b * Dd * Nn + n + (size_t)(qtr * 32) * Nn;
        #pragma unroll 4
        for (int d4 = 0; d4 < 8; d4++) {
            float4 v = er[d4];
            op[(size_t)(d4 * 4 + 0) * Nn] = v.x;
            op[(size_t)(d4 * 4 + 1) * Nn] = v.y;
            op[(size_t)(d4 * 4 + 2) * Nn] = v.z;
            op[(size_t)(d4 * 4 + 3) * Nn] = v.w;
        }
        float* zs = g_zsum + (size_t)ci * Dd + qtr * 32;
        uint32_t arow = (uint32_t)(tl * ARS_B + qtr * 64);
        #pragma unroll
        for (int c8 = 0; c8 < 4; c8++) {
            uint4 v0 = *(const uint4*)(smem_c + OFF_A + arow + c8 * 16);
            uint4 v1 = *(const uint4*)(smem_c + OFF_A + AB + arow + c8 * 16);
            const __half* p0 = (const __half*)&v0;
            const __half* p1 = (const __half*)&v1;
            #pragma unroll
            for (int e = 0; e < 8; e++) {
                float ze = fmaf(__half2float(p1[e]), SINV, __half2float(p0[e]));
                atomicAdd(&zs[c8 * 8 + e], ze);
            }
        }
    }
}

// ---------------------------------------------------------------------------
// K4: finalize EMA outputs
// ---------------------------------------------------------------------------
__global__ void vq_ema_kernel(const float* __restrict__ numer,
                              const float* __restrict__ denom,
                              float* __restrict__ out)
{
    int i = blockIdx.x * blockDim.x + threadIdx.x;
    out[NUM_OFF + i] = 0.99f * numer[i] + 0.01f * g_zsum[i];
    if (i < Kk)
        out[DEN_OFF + i] = 0.99f * denom[i] + 0.01f * g_nsum[i];
}

// ---------------------------------------------------------------------------
extern "C" void kernel_launch(void* const* d_in, const int* in_sizes, int n_in,
                              void* d_out, int out_size)
{
    const float* z     = (const float*)d_in[0];
    const float* W     = (const float*)d_in[1];
    const float* emb   = (const float*)d_in[2];
    const float* numer = (const float*)d_in[3];
    const float* denom = (const float*)d_in[4];
    float* out = (float*)d_out;

    cudaFuncSetAttribute(vq_ze_mma,
                         cudaFuncAttributeMaxDynamicSharedMemorySize, SM_ZE);
    cudaFuncSetAttribute(vq_dist_kernel,
                         cudaFuncAttributeMaxDynamicSharedMemorySize, SM_TOTAL);

    vq_prep_kernel<<<Kk, Dd>>>(emb);
    vq_prep_w_kernel<<<Dd, NIN>>>(W);
    vq_ze_mma<<<TOK / TPC, 256, SM_ZE>>>(z);
    vq_dist_kernel<<<TOK / TPC, 256, SM_TOTAL>>>(emb, out);
    vq_ema_kernel<<<(Kk * Dd) / 256, 256>>>(numer, denom, out);
}